// round 12
// baseline (speedup 1.0000x reference)
#include <cuda_runtime.h>
#include <cuda_bf16.h>
#include <math.h>
#include <stdint.h>

// ---------------- problem constants ----------------
#define BB      32
#define CC      3
#define IMG     224
#define NP      14
#define PS      16
#define IN_DIM  768
#define DD      768
#define NH      12
#define DH      64
#define LL      12
#define MLPD    3072
#define OUTC    1000
#define SS      197          // NP*NP + 1
#define NTOK    (BB*SS)      // 6304
#define NPATCH  (BB*NP*NP)   // 6272
#define MPAD    6400         // NTOK padded to 50*128

#define KA1     (2*DD)       // 1536: A storage [hi|lo]
#define KB1     (3*DD)       // 2304: B storage [hi|hi|lo]
#define KA2     (2*MLPD)     // 6144
#define KB2     (3*MLPD)     // 9216

#define SPAD    208          // padded seq len for attention tiles
#define VTP     232          // V^T row pitch (elems)

// ---------------- scratch (device globals; no runtime alloc) ----------------
static __device__ float g_resid[NTOK*DD];
static __device__ __nv_bfloat16 g_xs[(size_t)MPAD*KA1];
static __device__ __nv_bfloat16 g_hs[(size_t)MPAD*KA2];
static __device__ __nv_bfloat16 g_w1p[(size_t)LL*MLPD*KB1];
static __device__ __nv_bfloat16 g_w2p[(size_t)LL*DD*KB2];
static __device__ __nv_bfloat16 g_wmapp[(size_t)DD*KB1];
static __device__ __nv_bfloat16 g_wqkv[(size_t)LL*3*NH*64*128];         // [e][hi|lo]
static __device__ __nv_bfloat16 g_qs[(size_t)BB*NH*SPAD*128 + 128*128]; // [bh][s][qh|ql] +pad
static __device__ __nv_bfloat16 g_ks[(size_t)BB*NH*SPAD*128];           // [bh][s][kh|kl]
static __device__ __nv_bfloat16 g_vt[(size_t)BB*NH*128*VTP];

// ================= tensor-core helpers =================
__device__ __forceinline__ uint32_t smem_u32(const void* p) {
    uint32_t a;
    asm("{ .reg .u64 t; cvta.to.shared.u64 t, %1; cvt.u32.u64 %0, t; }" : "=r"(a) : "l"(p));
    return a;
}
__device__ __forceinline__ void cp_async16(uint32_t smem, const void* g) {
    asm volatile("cp.async.cg.shared.global [%0], [%1], 16;" :: "r"(smem), "l"(g));
}
#define CP_COMMIT() asm volatile("cp.async.commit_group;" ::: "memory")
#define CP_WAIT1()  asm volatile("cp.async.wait_group 1;" ::: "memory")
#define CP_WAIT0()  asm volatile("cp.async.wait_group 0;" ::: "memory")

__device__ __forceinline__ void ldmx4(uint32_t* r, uint32_t addr) {
    asm volatile("ldmatrix.sync.aligned.m8n8.x4.shared.b16 {%0,%1,%2,%3}, [%4];"
        : "=r"(r[0]), "=r"(r[1]), "=r"(r[2]), "=r"(r[3]) : "r"(addr));
}
__device__ __forceinline__ void mma16816(float* d, const uint32_t* a, uint32_t b0, uint32_t b1) {
    asm volatile(
        "mma.sync.aligned.m16n8k16.row.col.f32.bf16.bf16.f32 "
        "{%0,%1,%2,%3}, {%4,%5,%6,%7}, {%8,%9}, {%0,%1,%2,%3};"
        : "+f"(d[0]), "+f"(d[1]), "+f"(d[2]), "+f"(d[3])
        : "r"(a[0]), "r"(a[1]), "r"(a[2]), "r"(a[3]), "r"(b0), "r"(b1));
}
__device__ __forceinline__ uint32_t pack_bf2(float x, float y) {
    __nv_bfloat162 t = __floats2bfloat162_rn(x, y);
    return *(uint32_t*)&t;
}
__device__ __forceinline__ unsigned short bfu(__nv_bfloat16 h) {
    return *(unsigned short*)&h;
}

// ---------------- patchify: gather + split bf16 [hi(768)|lo(768)] ----------------
__global__ void patchify_kernel(const float* __restrict__ x, __nv_bfloat16* __restrict__ xs)
{
    int m = blockIdx.x;                 // 0..6271
    int b = m / (NP*NP);
    int p = m % (NP*NP);
    int py = p / NP, px = p % NP;
    for (int i = threadIdx.x; i < IN_DIM; i += blockDim.x) {
        int c = i >> 8;
        int r = (i >> 4) & 15;
        int s = i & 15;
        size_t src = ((size_t)(b*CC + c)*IMG + (py*PS + r))*IMG + (px*PS + s);
        float v = x[src];
        __nv_bfloat16 hi = __float2bfloat16(v);
        __nv_bfloat16 lo = __float2bfloat16(v - __bfloat162float(hi));
        xs[(size_t)m*KA1 + i]      = hi;
        xs[(size_t)m*KA1 + DD + i] = lo;
    }
}

__global__ void cls_init_kernel(const float* __restrict__ cls_emb,
                                const float* __restrict__ pos,
                                float* __restrict__ resid)
{
    int b = blockIdx.x;
    for (int d = threadIdx.x; d < DD; d += blockDim.x)
        resid[(size_t)b*SS*DD + d] = cls_emb[d] + pos[d];
}

// ---------------- weight prep: transpose + bf16 split, stacked K ----------------
__global__ void wprep_kernel(const float* __restrict__ W, __nv_bfloat16* __restrict__ Wp,
                             int K, int N)
{
    __shared__ float t[32][33];
    int l = blockIdx.z;
    const float* Wl = W + (size_t)l*K*N;
    __nv_bfloat16* Wpl = Wp + (size_t)l*N*3*K;
    int n0 = blockIdx.x*32, k0 = blockIdx.y*32;
    int tx = threadIdx.x, ty = threadIdx.y;

    t[ty][tx] = Wl[(size_t)(k0+ty)*N + n0+tx];
    __syncthreads();
    float v = t[tx][ty];
    int row = n0+ty, col = k0+tx;
    __nv_bfloat16 hi = __float2bfloat16(v);
    __nv_bfloat16 lo = __float2bfloat16(v - __bfloat162float(hi));
    __nv_bfloat16* dst = Wpl + (size_t)row*3*K;
    dst[col]       = hi;
    dst[K + col]   = hi;
    dst[2*K + col] = lo;
}

// ---------------- QKV weight prep: [e][hi(64)|lo(64)] ----------------
__global__ void qkv_prep_kernel(const float* __restrict__ Wq, const float* __restrict__ Wk,
                                const float* __restrict__ Wv, __nv_bfloat16* __restrict__ wout)
{
    int h = blockIdx.x, mat = blockIdx.y, l = blockIdx.z;
    const float* W = (mat == 0) ? Wq : (mat == 1) ? Wk : Wv;
    const float* Wl = W + (size_t)(l*NH + h)*64*64;
    __nv_bfloat16* dst = wout + (size_t)((l*3 + mat)*NH + h)*64*128;
    for (int idx = threadIdx.x; idx < 4096; idx += 256) {
        int e = idx >> 6, d = idx & 63;
        float v = Wl[e*64 + d];
        __nv_bfloat16 hi = __float2bfloat16(v);
        __nv_bfloat16 lo = __float2bfloat16(v - __bfloat162float(hi));
        dst[e*128 + d]      = hi;
        dst[e*128 + 64 + d] = lo;
    }
}

// ---------------- LayerNorm (192 threads, float4) -> split bf16 [hi|lo] --------
__global__ void ln_kernel(const float* __restrict__ xin, const float* __restrict__ g,
                          const float* __restrict__ bet, __nv_bfloat16* __restrict__ xs)
{
    int row = blockIdx.x;
    int tid = threadIdx.x;                 // 0..191
    const float4* xr = (const float4*)(xin + (size_t)row*DD);
    float4 v = xr[tid];
    float s  = v.x + v.y + v.z + v.w;
    float ss = v.x*v.x + v.y*v.y + v.z*v.z + v.w*v.w;

    __shared__ float rs[6], rss[6], smv[2];
    int lane = tid & 31, w = tid >> 5;
#pragma unroll
    for (int off = 16; off; off >>= 1) {
        s  += __shfl_xor_sync(0xffffffffu, s,  off);
        ss += __shfl_xor_sync(0xffffffffu, ss, off);
    }
    if (lane == 0) { rs[w] = s; rss[w] = ss; }
    __syncthreads();
    if (tid == 0) {
        float S = 0.f, SSq = 0.f;
#pragma unroll
        for (int i = 0; i < 6; i++) { S += rs[i]; SSq += rss[i]; }
        float mean = S * (1.f/768.f);
        float var  = SSq * (1.f/768.f) - mean*mean;
        smv[0] = mean;
        smv[1] = rsqrtf(var + 1e-5f);
    }
    __syncthreads();
    float mean = smv[0], rstd = smv[1];

    float4 gg = ((const float4*)g)[tid];
    float4 bb = ((const float4*)bet)[tid];
    float y0 = (v.x - mean)*rstd*gg.x + bb.x;
    float y1 = (v.y - mean)*rstd*gg.y + bb.y;
    float y2 = (v.z - mean)*rstd*gg.z + bb.z;
    float y3 = (v.w - mean)*rstd*gg.w + bb.w;
    __nv_bfloat16 h0 = __float2bfloat16(y0);
    __nv_bfloat16 h1 = __float2bfloat16(y1);
    __nv_bfloat16 h2 = __float2bfloat16(y2);
    __nv_bfloat16 h3 = __float2bfloat16(y3);
    uint32_t hi01 = (uint32_t)bfu(h0) | ((uint32_t)bfu(h1) << 16);
    uint32_t hi23 = (uint32_t)bfu(h2) | ((uint32_t)bfu(h3) << 16);
    uint32_t lo01 = pack_bf2(y0 - __bfloat162float(h0), y1 - __bfloat162float(h1));
    uint32_t lo23 = pack_bf2(y2 - __bfloat162float(h2), y3 - __bfloat162float(h3));
    __nv_bfloat16* dst = xs + (size_t)row*KA1;
    *(uint2*)(dst + tid*4)      = make_uint2(hi01, hi23);
    *(uint2*)(dst + DD + tid*4) = make_uint2(lo01, lo23);
}

// ---------------- HMMA GEMM, 128x128 tile (GEMM1 + embed) ----------------
template<int MODE>
__global__ void __launch_bounds__(256, 2)
mma_mlp_kernel(const __nv_bfloat16* __restrict__ A, const __nv_bfloat16* __restrict__ Bw,
               const float* __restrict__ bias, __nv_bfloat16* __restrict__ hs_out,
               float* __restrict__ resid, int nk, int strideA, int strideB,
               const float* __restrict__ extra)
{
    extern __shared__ char smc[];
    const uint32_t sbase = smem_u32(smc);
    const int tid = threadIdx.x;
    const int wid = tid >> 5, lane = tid & 31;
    const int wm = wid & 1, wn = wid >> 1;
    const int bx = blockIdx.x, by = blockIdx.y;
    const int NC = 3*nk;

    const __nv_bfloat16* Abase = A + (size_t)(by*128)*strideA;
    const __nv_bfloat16* Bbase = Bw + (size_t)(bx*128)*strideB;

    float acc[4][4][4];
#pragma unroll
    for (int i = 0; i < 4; i++)
#pragma unroll
        for (int j = 0; j < 4; j++)
#pragma unroll
            for (int q = 0; q < 4; q++) acc[i][j][q] = 0.f;

    const int lq = tid & 7;
    const int lr = tid >> 3;

    auto load_chunk = [&](int c, int p) {
        int cwrap = (c < 2*nk) ? c : (c - 2*nk);
        const __nv_bfloat16* Ap = Abase + (size_t)cwrap*64;
        const __nv_bfloat16* Bp = Bbase + (size_t)c*64;
        uint32_t sA = sbase + p*32768;
        uint32_t sB = sA + 16384;
#pragma unroll
        for (int i = 0; i < 4; i++) {
            int r = i*32 + lr;
            uint32_t off = r*128 + lq*16;
            uint32_t sw = off ^ ((off >> 3) & 0x70);
            cp_async16(sA + sw, Ap + (size_t)r*strideA + lq*8);
            cp_async16(sB + sw, Bp + (size_t)r*strideB + lq*8);
        }
        CP_COMMIT();
    };

    const int l15 = lane & 15;
    const int lks = (lane >> 4) * 16;

    load_chunk(0, 0);

    for (int c = 0; c < NC; c++) {
        int p = c & 1;
        if (c + 1 < NC) { load_chunk(c+1, (c+1)&1); CP_WAIT1(); }
        else            { CP_WAIT0(); }
        __syncthreads();

        uint32_t sA = sbase + p*32768;
        uint32_t sB = sA + 16384;
#pragma unroll
        for (int ks = 0; ks < 4; ks++) {
            uint32_t b0[4], b1[4];
            {
                uint32_t off = (wn*32 + l15)*128 + ks*32 + lks;
                ldmx4(b0, sB + (off ^ ((off >> 3) & 0x70)));
                off = (wn*32 + 16 + l15)*128 + ks*32 + lks;
                ldmx4(b1, sB + (off ^ ((off >> 3) & 0x70)));
            }
#pragma unroll
            for (int mt = 0; mt < 4; mt++) {
                uint32_t a[4];
                uint32_t off = (wm*64 + mt*16 + l15)*128 + ks*32 + lks;
                ldmx4(a, sA + (off ^ ((off >> 3) & 0x70)));
                mma16816(acc[mt][0], a, b0[0], b0[2]);
                mma16816(acc[mt][1], a, b0[1], b0[3]);
                mma16816(acc[mt][2], a, b1[0], b1[2]);
                mma16816(acc[mt][3], a, b1[1], b1[3]);
            }
        }
        __syncthreads();
    }

    const int gm0 = by*128 + wm*64 + (lane >> 2);
    const int gn0 = bx*128 + wn*32 + (lane & 3)*2;

#pragma unroll
    for (int mt = 0; mt < 4; mt++) {
#pragma unroll
        for (int nt = 0; nt < 4; nt++) {
            int col = gn0 + nt*8;
            float bi0 = bias[col], bi1 = bias[col+1];
            int r0 = gm0 + mt*16;
            int r1 = r0 + 8;
            float v00 = acc[mt][nt][0] + bi0;
            float v01 = acc[mt][nt][1] + bi1;
            float v10 = acc[mt][nt][2] + bi0;
            float v11 = acc[mt][nt][3] + bi1;
            if (MODE == 0) {
                float g00 = 0.5f*v00*(1.f + erff(v00*0.70710678118654752f));
                float g01 = 0.5f*v01*(1.f + erff(v01*0.70710678118654752f));
                float g10 = 0.5f*v10*(1.f + erff(v10*0.70710678118654752f));
                float g11 = 0.5f*v11*(1.f + erff(v11*0.70710678118654752f));
                __nv_bfloat16 h00 = __float2bfloat16(g00);
                __nv_bfloat16 h01 = __float2bfloat16(g01);
                __nv_bfloat16 h10 = __float2bfloat16(g10);
                __nv_bfloat16 h11 = __float2bfloat16(g11);
                uint32_t hi0 = (uint32_t)bfu(h00) | ((uint32_t)bfu(h01) << 16);
                uint32_t hi1 = (uint32_t)bfu(h10) | ((uint32_t)bfu(h11) << 16);
                uint32_t lo0 = pack_bf2(g00 - __bfloat162float(h00), g01 - __bfloat162float(h01));
                uint32_t lo1 = pack_bf2(g10 - __bfloat162float(h10), g11 - __bfloat162float(h11));
                if (r0 < NTOK) {
                    *(uint32_t*)(hs_out + (size_t)r0*KA2 + col)        = hi0;
                    *(uint32_t*)(hs_out + (size_t)r0*KA2 + MLPD + col) = lo0;
                }
                if (r1 < NTOK) {
                    *(uint32_t*)(hs_out + (size_t)r1*KA2 + col)        = hi1;
                    *(uint32_t*)(hs_out + (size_t)r1*KA2 + MLPD + col) = lo1;
                }
            } else { // MODE 2: embed epilogue
                {
                    int pp = r0 % (NP*NP), bb = r0 / (NP*NP);
                    int orow = bb*SS + 1 + pp;
                    float2* p = (float2*)(resid + (size_t)orow*DD + col);
                    const float2* e = (const float2*)(extra + (size_t)(pp+1)*DD + col);
                    float2 ev = *e;
                    *p = make_float2(v00 + ev.x, v01 + ev.y);
                }
                {
                    int pp = r1 % (NP*NP), bb = r1 / (NP*NP);
                    int orow = bb*SS + 1 + pp;
                    float2* p = (float2*)(resid + (size_t)orow*DD + col);
                    const float2* e = (const float2*)(extra + (size_t)(pp+1)*DD + col);
                    float2 ev = *e;
                    *p = make_float2(v10 + ev.x, v11 + ev.y);
                }
            }
        }
    }
}

// ---------------- HMMA GEMM2: 128x64 tiles, occ 3 ----------
__global__ void __launch_bounds__(256, 3)
mma_g2_kernel(const __nv_bfloat16* __restrict__ A, const __nv_bfloat16* __restrict__ Bw,
              const float* __restrict__ bias, float* __restrict__ resid,
              int nk, int strideA, int strideB)
{
    extern __shared__ char smc[];
    const uint32_t sbase = smem_u32(smc);
    const int tid = threadIdx.x;
    const int wid = tid >> 5, lane = tid & 31;
    const int wm = wid & 3, wn = wid >> 2;
    const int bx = blockIdx.x, by = blockIdx.y;
    const int NC = 3*nk;

    const __nv_bfloat16* Abase = A + (size_t)(by*128)*strideA;
    const __nv_bfloat16* Bbase = Bw + (size_t)(bx*64)*strideB;

    float acc[2][4][4];
#pragma unroll
    for (int i = 0; i < 2; i++)
#pragma unroll
        for (int j = 0; j < 4; j++)
#pragma unroll
            for (int q = 0; q < 4; q++) acc[i][j][q] = 0.f;

    const int lq = tid & 7;
    const int lr = tid >> 3;

    auto load_chunk = [&](int c, int p) {
        int cwrap = (c < 2*nk) ? c : (c - 2*nk);
        const __nv_bfloat16* Ap = Abase + (size_t)cwrap*64;
        const __nv_bfloat16* Bp = Bbase + (size_t)c*64;
        uint32_t sA = sbase + p*24576;
        uint32_t sB = sA + 16384;
#pragma unroll
        for (int i = 0; i < 4; i++) {
            int r = i*32 + lr;
            uint32_t off = r*128 + lq*16;
            uint32_t sw = off ^ ((off >> 3) & 0x70);
            cp_async16(sA + sw, Ap + (size_t)r*strideA + lq*8);
        }
#pragma unroll
        for (int i = 0; i < 2; i++) {
            int r = i*32 + lr;
            uint32_t off = r*128 + lq*16;
            uint32_t sw = off ^ ((off >> 3) & 0x70);
            cp_async16(sB + sw, Bp + (size_t)r*strideB + lq*8);
        }
        CP_COMMIT();
    };

    const int l15 = lane & 15;
    const int lks = (lane >> 4) * 16;

    load_chunk(0, 0);

    for (int c = 0; c < NC; c++) {
        int p = c & 1;
        if (c + 1 < NC) { load_chunk(c+1, (c+1)&1); CP_WAIT1(); }
        else            { CP_WAIT0(); }
        __syncthreads();

        uint32_t sA = sbase + p*24576;
        uint32_t sB = sA + 16384;
#pragma unroll
        for (int ks = 0; ks < 4; ks++) {
            uint32_t b0[4], b1[4];
            {
                uint32_t off = (wn*32 + l15)*128 + ks*32 + lks;
                ldmx4(b0, sB + (off ^ ((off >> 3) & 0x70)));
                off = (wn*32 + 16 + l15)*128 + ks*32 + lks;
                ldmx4(b1, sB + (off ^ ((off >> 3) & 0x70)));
            }
#pragma unroll
            for (int mt = 0; mt < 2; mt++) {
                uint32_t a[4];
                uint32_t off = (wm*32 + mt*16 + l15)*128 + ks*32 + lks;
                ldmx4(a, sA + (off ^ ((off >> 3) & 0x70)));
                mma16816(acc[mt][0], a, b0[0], b0[2]);
                mma16816(acc[mt][1], a, b0[1], b0[3]);
                mma16816(acc[mt][2], a, b1[0], b1[2]);
                mma16816(acc[mt][3], a, b1[1], b1[3]);
            }
        }
        __syncthreads();
    }

    const int gm0 = by*128 + wm*32 + (lane >> 2);
    const int gn0 = bx*64 + wn*32 + (lane & 3)*2;

#pragma unroll
    for (int mt = 0; mt < 2; mt++) {
#pragma unroll
        for (int nt = 0; nt < 4; nt++) {
            int col = gn0 + nt*8;
            float bi0 = bias[col], bi1 = bias[col+1];
            int r0 = gm0 + mt*16;
            int r1 = r0 + 8;
            if (r0 < NTOK) {
                float2* p = (float2*)(resid + (size_t)r0*DD + col);
                float2 t = *p;
                t.x += acc[mt][nt][0] + bi0;
                t.y += acc[mt][nt][1] + bi1;
                *p = t;
            }
            if (r1 < NTOK) {
                float2* p = (float2*)(resid + (size_t)r1*DD + col);
                float2 t = *p;
                t.x += acc[mt][nt][2] + bi0;
                t.y += acc[mt][nt][3] + bi1;
                *p = t;
            }
        }
    }
}

// ---------------- HMMA QKV projection: q/k 2-section [hi|lo], v transposed ----
__global__ void __launch_bounds__(128, 3)
qkv_mma_kernel(const __nv_bfloat16* __restrict__ xs, const __nv_bfloat16* __restrict__ wqkv,
               const float* __restrict__ bq, const float* __restrict__ bk,
               const float* __restrict__ bv,
               __nv_bfloat16* __restrict__ qsd, __nv_bfloat16* __restrict__ ksd,
               __nv_bfloat16* __restrict__ vtd)
{
    extern __shared__ char smc[];
    const uint32_t sbase = smem_u32(smc);
    const int tid = threadIdx.x;
    const int wid = tid >> 5, lane = tid & 31;
    const int hm = blockIdx.x;
    const int mat = hm / NH, h = hm % NH;
    const int by = blockIdx.y;

    const __nv_bfloat16* Wp = wqkv + (size_t)hm*64*128;
    const float* bias = (mat == 0) ? bq : (mat == 1) ? bk : bv;

    const int lq = tid & 7, lr = tid >> 3;
#pragma unroll
    for (int c = 0; c < 2; c++) {
        const __nv_bfloat16* Ap = xs + (c ? (DD + h*64) : (h*64));
#pragma unroll
        for (int i = 0; i < 8; i++) {
            int r = i*16 + lr;
            uint32_t off = r*128 + lq*16;
            uint32_t sw = off ^ ((off >> 3) & 0x70);
            cp_async16(sbase + c*16384 + sw, Ap + (size_t)(by*128 + r)*KA1 + lq*8);
        }
    }
#pragma unroll
    for (int c = 0; c < 2; c++) {      // B buffers: 0 = hi, 1 = lo
#pragma unroll
        for (int i = 0; i < 4; i++) {
            int r = i*16 + lr;
            uint32_t off = r*128 + lq*16;
            uint32_t sw = off ^ ((off >> 3) & 0x70);
            cp_async16(sbase + 32768 + c*8192 + sw, Wp + (size_t)r*128 + c*64 + lq*8);
        }
    }
    CP_COMMIT();
    CP_WAIT0();
    __syncthreads();

    float acc[2][8][4];
#pragma unroll
    for (int i = 0; i < 2; i++)
#pragma unroll
        for (int j = 0; j < 8; j++)
#pragma unroll
            for (int t = 0; t < 4; t++) acc[i][j][t] = 0.f;

    const int l15 = lane & 15;
    const int lks = (lane >> 4) * 16;
    const int m0 = wid*32;

    // pass 0: Ah*Wh, pass 1: Al*Wh, pass 2: Ah*Wl
#pragma unroll
    for (int pass = 0; pass < 3; pass++) {
        uint32_t sA = sbase + ((pass == 1) ? 16384 : 0);
        uint32_t sB = sbase + 32768 + ((pass == 2) ? 8192 : 0);
#pragma unroll
        for (int ks = 0; ks < 4; ks++) {
            uint32_t b[4][4];
#pragma unroll
            for (int nb = 0; nb < 4; nb++) {
                uint32_t off = (nb*16 + l15)*128 + ks*32 + lks;
                ldmx4(b[nb], sB + (off ^ ((off >> 3) & 0x70)));
            }
#pragma unroll
            for (int mt = 0; mt < 2; mt++) {
                uint32_t a[4];
                uint32_t off = (m0 + mt*16 + l15)*128 + ks*32 + lks;
                ldmx4(a, sA + (off ^ ((off >> 3) & 0x70)));
#pragma unroll
                for (int nb = 0; nb < 4; nb++) {
                    mma16816(acc[mt][2*nb],   a, b[nb][0], b[nb][2]);
                    mma16816(acc[mt][2*nb+1], a, b[nb][1], b[nb][3]);
                }
            }
        }
    }

    const int c0 = (lane & 3)*2;
#pragma unroll
    for (int mt = 0; mt < 2; mt++) {
#pragma unroll
        for (int nt = 0; nt < 8; nt++) {
            int e = nt*8 + c0;
            float bi0 = bias[h*64 + e], bi1 = bias[h*64 + e + 1];
            int r0 = by*128 + m0 + mt*16 + (lane >> 2);
#pragma unroll
            for (int half = 0; half < 2; half++) {
                int r = r0 + half*8;
                if (r >= NTOK) continue;
                float v0 = acc[mt][nt][2*half]   + bi0;
                float v1 = acc[mt][nt][2*half+1] + bi1;
                __nv_bfloat16 h0 = __float2bfloat16(v0);
                __nv_bfloat16 h1 = __float2bfloat16(v1);
                float l0 = v0 - __bfloat162float(h0);
                float l1 = v1 - __bfloat162float(h1);
                int b = r / SS, s = r % SS;
                int bh = b*NH + h;
                if (mat == 2) {
                    __nv_bfloat16* vb = vtd + (size_t)bh*128*VTP;
                    vb[(size_t)e*VTP + s]          = h0;
                    vb[(size_t)(e+1)*VTP + s]      = h1;
                    vb[(size_t)(64+e)*VTP + s]     = __float2bfloat16(l0);
                    vb[(size_t)(64+e+1)*VTP + s]   = __float2bfloat16(l1);
                } else {
                    uint32_t hi = (uint32_t)bfu(h0) | ((uint32_t)bfu(h1) << 16);
                    uint32_t lo = pack_bf2(l0, l1);
                    __nv_bfloat16* base = (mat == 0 ? qsd : ksd) + ((size_t)bh*SPAD + s)*128;
                    *(uint32_t*)(base + e)      = hi;
                    *(uint32_t*)(base + 64 + e) = lo;
                }
            }
        }
    }
}

// ---------------- HMMA fused attention: dual-plane Q/K (round-10 proven) -------
#define AK_PLANE 26624     // 208*128
__global__ void __launch_bounds__(256, 1)
attn_mma_kernel(const __nv_bfloat16* __restrict__ qsd, const __nv_bfloat16* __restrict__ ksd,
                const __nv_bfloat16* __restrict__ vtd, float* __restrict__ resid)
{
    extern __shared__ char smc[];
    const uint32_t sbase = smem_u32(smc);
    const uint32_t sQ = sbase;                         // 2 planes x 16384
    const uint32_t sK = sbase + 32768;                 // 2 planes x 26624
    const uint32_t sV = sbase + 32768 + 2*AK_PLANE;    // 128 x 464

    const int tid = threadIdx.x;
    const int wid = tid >> 5, lane = tid & 31;
    const int qt = blockIdx.x, bh = blockIdx.y;
    const int b = bh / NH, h = bh % NH;

    const __nv_bfloat16* Qg = qsd + ((size_t)bh*SPAD + (size_t)qt*128)*128;
    const __nv_bfloat16* Kg = ksd + (size_t)bh*SPAD*128;
    const __nv_bfloat16* Vg = vtd + (size_t)bh*128*VTP;

    // group 0: Q + K (global rows are 256B = [hi 128B | lo 128B] -> two planes)
    for (int i = tid; i < 128*16; i += 256) {
        int r = i >> 4, c = i & 15;
        uint32_t pl = (c < 8) ? 0u : 16384u;
        uint32_t off = r*128 + (c & 7)*16;
        cp_async16(sQ + pl + (off ^ ((off >> 3) & 0x70)), Qg + (size_t)r*128 + c*8);
    }
    for (int i = tid; i < SPAD*16; i += 256) {
        int r = i >> 4, c = i & 15;
        uint32_t pl = (c < 8) ? 0u : (uint32_t)AK_PLANE;
        uint32_t off = r*128 + (c & 7)*16;
        cp_async16(sK + pl + (off ^ ((off >> 3) & 0x70)), Kg + (size_t)r*128 + c*8);
    }
    CP_COMMIT();
    // group 1: V^T
    for (int i = tid; i < 128*29; i += 256) {
        int r = i / 29, c = i % 29;
        cp_async16(sV + r*464 + c*16, Vg + (size_t)r*VTP + c*8);
    }
    CP_COMMIT();
    CP_WAIT1();
    __syncthreads();

    float s[26][4];
#pragma unroll
    for (int t = 0; t < 26; t++)
#pragma unroll
        for (int e = 0; e < 4; e++) s[t][e] = 0.f;

    const int l15 = lane & 15;
    const int lks = (lane >> 4) * 16;
    const int m0 = wid * 16;

    // stacked K=192: kc0-3 Qh*Kh, kc4-7 Ql*Kh, kc8-11 Qh*Kl
#pragma unroll 1
    for (int kc = 0; kc < 12; kc++) {
        uint32_t qpl = (kc >= 4 && kc < 8) ? 16384u : 0u;
        uint32_t kpl = (kc >= 8) ? (uint32_t)AK_PLANE : 0u;
        int cb = (kc & 3)*32;
        uint32_t a[4];
        uint32_t off = (m0 + l15)*128 + cb + lks;
        ldmx4(a, sQ + qpl + (off ^ ((off >> 3) & 0x70)));
#pragma unroll
        for (int nb = 0; nb < 13; nb++) {
            uint32_t bb[4];
            off = (nb*16 + l15)*128 + cb + lks;
            ldmx4(bb, sK + kpl + (off ^ ((off >> 3) & 0x70)));
            mma16816(s[2*nb],   a, bb[0], bb[2]);
            mma16816(s[2*nb+1], a, bb[1], bb[3]);
        }
    }

    const int c0 = 2*(lane & 3);
    float mx0 = -1e30f, mx1 = -1e30f;
#pragma unroll
    for (int t = 0; t < 26; t++) {
        int j0 = t*8 + c0;
        float v0 = (j0   < SS) ? s[t][0]*0.125f : -1e30f;
        float v1 = (j0+1 < SS) ? s[t][1]*0.125f : -1e30f;
        float v2 = (j0   < SS) ? s[t][2]*0.125f : -1e30f;
        float v3 = (j0+1 < SS) ? s[t][3]*0.125f : -1e30f;
        s[t][0] = v0; s[t][1] = v1; s[t][2] = v2; s[t][3] = v3;
        mx0 = fmaxf(mx0, fmaxf(v0, v1));
        mx1 = fmaxf(mx1, fmaxf(v2, v3));
    }
    mx0 = fmaxf(mx0, __shfl_xor_sync(0xffffffffu, mx0, 1));
    mx0 = fmaxf(mx0, __shfl_xor_sync(0xffffffffu, mx0, 2));
    mx1 = fmaxf(mx1, __shfl_xor_sync(0xffffffffu, mx1, 1));
    mx1 = fmaxf(mx1, __shfl_xor_sync(0xffffffffu, mx1, 2));

    float sum0 = 0.f, sum1 = 0.f;
#pragma unroll
    for (int t = 0; t < 26; t++) {
        float p0 = __expf(s[t][0] - mx0);
        float p1 = __expf(s[t][1] - mx0);
        float p2 = __expf(s[t][2] - mx1);
        float p3 = __expf(s[t][3] - mx1);
        s[t][0] = p0; s[t][1] = p1; s[t][2] = p2; s[t][3] = p3;
        sum0 += p0 + p1;
        sum1 += p2 + p3;
    }
    sum0 += __shfl_xor_sync(0xffffffffu, sum0, 1);
    sum0 += __shfl_xor_sync(0xffffffffu, sum0, 2);
    sum1 += __shfl_xor_sync(0xffffffffu, sum1, 1);
    sum1 += __shfl_xor_sync(0xffffffffu, sum1, 2);
    float inv0 = 1.f / sum0, inv1 = 1.f / sum1;

    CP_WAIT0();
    __syncthreads();

    float o[8][4];
#pragma unroll
    for (int t = 0; t < 8; t++)
#pragma unroll
        for (int e = 0; e < 4; e++) o[t][e] = 0.f;

#pragma unroll 1
    for (int kt = 0; kt < 13; kt++) {
        uint32_t ah[4], al[4];
        {
            float p00 = s[2*kt][0],   p01 = s[2*kt][1],   p02 = s[2*kt][2],   p03 = s[2*kt][3];
            float p10 = s[2*kt+1][0], p11 = s[2*kt+1][1], p12 = s[2*kt+1][2], p13 = s[2*kt+1][3];
            __nv_bfloat16 h00 = __float2bfloat16(p00), h01 = __float2bfloat16(p01);
            __nv_bfloat16 h02 = __float2bfloat16(p02), h03 = __float2bfloat16(p03);
            __nv_bfloat16 h10 = __float2bfloat16(p10), h11 = __float2bfloat16(p11);
            __nv_bfloat16 h12 = __float2bfloat16(p12), h13 = __float2bfloat16(p13);
            ah[0] = (uint32_t)bfu(h00) | ((uint32_t)bfu(h01) << 16);
            ah[1] = (uint32_t)bfu(h02) | ((uint32_t)bfu(h03) << 16);
            ah[2] = (uint32_t)bfu(h10) | ((uint32_t)bfu(h11) << 16);
            ah[3] = (uint32_t)bfu(h12) | ((uint32_t)bfu(h13) << 16);
            al[0] = pack_bf2(p00 - __bfloat162float(h00), p01 - __bfloat162float(h01));
            al[1] = pack_bf2(p02 - __bfloat162float(h02), p03 - __bfloat162float(h03));
            al[2] = pack_bf2(p10 - __bfloat162float(h10), p11 - __bfloat162float(h11));
            al[3] = pack_bf2(p12 - __bfloat162float(h12), p13 - __bfloat162float(h13));
        }
#pragma unroll
        for (int nb = 0; nb < 4; nb++) {
            uint32_t bh_[4], bl_[4];
            ldmx4(bh_, sV + (nb*16 + l15)*464 + kt*32 + lks);
            ldmx4(bl_, sV + (64 + nb*16 + l15)*464 + kt*32 + lks);
            mma16816(o[2*nb],   ah, bh_[0], bh_[2]);
            mma16816(o[2*nb+1], ah, bh_[1], bh_[3]);
            mma16816(o[2*nb],   al, bh_[0], bh_[2]);
            mma16816(o[2*nb+1], al, bh_[1], bh_[3]);
            mma16816(o[2*nb],   ah, bl_[0], bl_[2]);
            mma16816(o[2*nb+1], ah, bl_[1], bl_[3]);
        }
    }

    const int r0 = qt*128 + m0 + (lane >> 2);
    const int r1 = r0 + 8;
#pragma unroll
    for (int nb = 0; nb < 8; nb++) {
        int col = h*64 + nb*8 + c0;
        if (r0 < SS) {
            float2* p = (float2*)(resid + ((size_t)(b*SS + r0))*DD + col);
            float2 t = *p;
            t.x += o[nb][0]*inv0;
            t.y += o[nb][1]*inv0;
            *p = t;
        }
        if (r1 < SS) {
            float2* p = (float2*)(resid + ((size_t)(b*SS + r1))*DD + col);
            float2 t = *p;
            t.x += o[nb][2]*inv1;
            t.y += o[nb][3]*inv1;
            *p = t;
        }
    }
}

// ---------------- classifier head ----------------
__global__ void head_kernel(const float* __restrict__ resid, const float* __restrict__ Wc,
                            const float* __restrict__ bc, float* __restrict__ out)
{
    __shared__ float sx[768];
    __shared__ float logit[1000];
    __shared__ float red[8];
    __shared__ float bscalar;

    int b = blockIdx.x;
    int tid = threadIdx.x;
    int lane = tid & 31, w = tid >> 5;

    for (int i = tid; i < 768; i += 256) sx[i] = resid[(size_t)b*SS*DD + i];
    __syncthreads();

    for (int o = tid; o < OUTC; o += 256) {
        float acc = bc[o];
        for (int kk = 0; kk < 768; kk++) acc += sx[kk]*Wc[(size_t)kk*OUTC + o];
        logit[o] = acc;
    }
    __syncthreads();

    float m = -1e30f;
    for (int o = tid; o < OUTC; o += 256) m = fmaxf(m, logit[o]);
#pragma unroll
    for (int off = 16; off; off >>= 1) m = fmaxf(m, __shfl_xor_sync(0xffffffffu, m, off));
    if (lane == 0) red[w] = m;
    __syncthreads();
    if (tid == 0) {
        float mm = red[0];
#pragma unroll
        for (int i = 1; i < 8; i++) mm = fmaxf(mm, red[i]);
        bscalar = mm;
    }
    __syncthreads();
    m = bscalar;

    float s = 0.f;
    for (int o = tid; o < OUTC; o += 256) {
        float e = __expf(logit[o] - m);
        logit[o] = e;
        s += e;
    }
#pragma unroll
    for (int off = 16; off; off >>= 1) s += __shfl_xor_sync(0xffffffffu, s, off);
    if (lane == 0) red[w] = s;
    __syncthreads();
    if (tid == 0) {
        float ssum = 0.f;
#pragma unroll
        for (int i = 0; i < 8; i++) ssum += red[i];
        bscalar = 1.f / ssum;
    }
    __syncthreads();
    float invs = bscalar;
    for (int o = tid; o < OUTC; o += 256)
        out[(size_t)b*OUTC + o] = logit[o] * invs;
}

// ---------------- launcher ----------------
extern "C" void kernel_launch(void* const* d_in, const int* in_sizes, int n_in,
                              void* d_out, int out_size)
{
    const float* x       = (const float*)d_in[0];
    const float* cls_emb = (const float*)d_in[1];
    const float* pos     = (const float*)d_in[2];
    const float* Wmap    = (const float*)d_in[3];
    const float* bmap    = (const float*)d_in[4];
    const float* ln1_g   = (const float*)d_in[5];
    const float* ln1_b   = (const float*)d_in[6];
    const float* Wq      = (const float*)d_in[7];
    const float* bq      = (const float*)d_in[8];
    const float* Wk      = (const float*)d_in[9];
    const float* bk      = (const float*)d_in[10];
    const float* Wv      = (const float*)d_in[11];
    const float* bv      = (const float*)d_in[12];
    const float* ln2_g   = (const float*)d_in[13];
    const float* ln2_b   = (const float*)d_in[14];
    const float* W1      = (const float*)d_in[15];
    const float* b1      = (const float*)d_in[16];
    const float* W2      = (const float*)d_in[17];
    const float* b2      = (const float*)d_in[18];
    const float* Wc      = (const float*)d_in[19];
    const float* bc      = (const float*)d_in[20];
    float* out = (float*)d_out;

    float *resid;
    __nv_bfloat16 *xs, *hs, *w1p, *w2p, *wmapp, *wqkv, *qsd, *ksd, *vtd;
    cudaGetSymbolAddress((void**)&resid, g_resid);
    cudaGetSymbolAddress((void**)&xs,    g_xs);
    cudaGetSymbolAddress((void**)&hs,    g_hs);
    cudaGetSymbolAddress((void**)&w1p,   g_w1p);
    cudaGetSymbolAddress((void**)&w2p,   g_w2p);
    cudaGetSymbolAddress((void**)&wmapp, g_wmapp);
    cudaGetSymbolAddress((void**)&wqkv,  g_wqkv);
    cudaGetSymbolAddress((void**)&qsd,   g_qs);
    cudaGetSymbolAddress((void**)&ksd,   g_ks);
    cudaGetSymbolAddress((void**)&vtd,   g_vt);

    const int MMA_SMEM  = 65536;
    const int G2_SMEM   = 49152;
    const int QKV_SMEM  = 2*16384 + 2*8192;             // 49,152 B
    const int ATTN_SMEM = 32768 + 2*AK_PLANE + 128*464; // 145,408 B
    cudaFuncSetAttribute(mma_mlp_kernel<0>, cudaFuncAttributeMaxDynamicSharedMemorySize, MMA_SMEM);
    cudaFuncSetAttribute(mma_mlp_kernel<2>, cudaFuncAttributeMaxDynamicSharedMemorySize, MMA_SMEM);
    cudaFuncSetAttribute(mma_g2_kernel, cudaFuncAttributeMaxDynamicSharedMemorySize, G2_SMEM);
    cudaFuncSetAttribute(qkv_mma_kernel, cudaFuncAttributeMaxDynamicSharedMemorySize, QKV_SMEM);
    cudaFuncSetAttribute(attn_mma_kernel, cudaFuncAttributeMaxDynamicSharedMemorySize, ATTN_SMEM);

    // weight prep
    wprep_kernel<<<dim3(MLPD/32, DD/32, LL), dim3(32,32)>>>(W1, w1p, DD, MLPD);
    wprep_kernel<<<dim3(DD/32, MLPD/32, LL), dim3(32,32)>>>(W2, w2p, MLPD, DD);
    wprep_kernel<<<dim3(DD/32, IN_DIM/32, 1), dim3(32,32)>>>(Wmap, wmapp, IN_DIM, DD);
    qkv_prep_kernel<<<dim3(NH, 3, LL), 256>>>(Wq, Wk, Wv, wqkv);

    // patch embed (split bf16 -> HMMA) + positional
    patchify_kernel<<<NPATCH, 256>>>(x, xs);
    mma_mlp_kernel<2><<<dim3(DD/128, NPATCH/128), 256, MMA_SMEM>>>(
        xs, wmapp, bmap, nullptr, resid, 12, KA1, KB1, pos);
    cls_init_kernel<<<BB, 256>>>(cls_emb, pos, resid);

    for (int l = 0; l < LL; l++) {
        ln_kernel<<<NTOK, 192>>>(resid, ln1_g + (size_t)l*DD, ln1_b + (size_t)l*DD, xs);
        qkv_mma_kernel<<<dim3(3*NH, MPAD/128), 128, QKV_SMEM>>>(
            xs, wqkv + (size_t)l*3*NH*64*128,
            bq + (size_t)l*NH*DH, bk + (size_t)l*NH*DH, bv + (size_t)l*NH*DH,
            qsd, ksd, vtd);
        attn_mma_kernel<<<dim3(2, BB*NH), 256, ATTN_SMEM>>>(qsd, ksd, vtd, resid);

        ln_kernel<<<NTOK, 192>>>(resid, ln2_g + (size_t)l*DD, ln2_b + (size_t)l*DD, xs);
        mma_mlp_kernel<0><<<dim3(MLPD/128, MPAD/128), 256, MMA_SMEM>>>(
            xs, w1p + (size_t)l*MLPD*KB1, b1 + (size_t)l*MLPD, hs, nullptr, 12, KA1, KB1, nullptr);
        mma_g2_kernel<<<dim3(DD/64, MPAD/128), 256, G2_SMEM>>>(
            hs, w2p + (size_t)l*DD*KB2, b2 + (size_t)l*DD, resid, 48, KA2, KB2);
    }

    head_kernel<<<BB, 256>>>(resid, Wc, bc, out);
}

// round 14
// speedup vs baseline: 1.5130x; 1.5130x over previous
#include <cuda_runtime.h>
#include <cuda_bf16.h>
#include <math.h>
#include <stdint.h>

// ---------------- problem constants ----------------
#define BB      32
#define CC      3
#define IMG     224
#define NP      14
#define PS      16
#define IN_DIM  768
#define DD      768
#define NH      12
#define DH      64
#define LL      12
#define MLPD    3072
#define OUTC    1000
#define SS      197          // NP*NP + 1
#define NTOK    (BB*SS)      // 6304
#define NPATCH  (BB*NP*NP)   // 6272
#define MPAD    6400         // NTOK padded to 50*128

#define KA1     (2*DD)       // 1536: A storage [hi|lo]
#define KB1     (3*DD)       // 2304: B storage [hi|hi|lo]
#define KA2     (2*MLPD)     // 6144
#define KB2     (3*MLPD)     // 9216

#define SPAD    208          // padded seq len for attention tiles
#define VTP     232          // V^T row pitch (elems)

// ---------------- scratch (device globals; no runtime alloc) ----------------
static __device__ float g_resid[NTOK*DD];
static __device__ __nv_bfloat16 g_xs[(size_t)MPAD*KA1];
static __device__ __nv_bfloat16 g_hs[(size_t)MPAD*KA2];
static __device__ __nv_bfloat16 g_w1p[(size_t)LL*MLPD*KB1];
static __device__ __nv_bfloat16 g_w2p[(size_t)LL*DD*KB2];
static __device__ __nv_bfloat16 g_wmapp[(size_t)DD*KB1];
static __device__ __nv_bfloat16 g_wqkv[(size_t)LL*3*NH*64*192];
static __device__ __nv_bfloat16 g_qs[(size_t)BB*NH*SPAD*128 + 128*128]; // [bh][s][qh|ql] +pad
static __device__ __nv_bfloat16 g_ks[(size_t)BB*NH*SPAD*128];           // [bh][s][kh|kl]
static __device__ __nv_bfloat16 g_vt[(size_t)BB*NH*128*VTP];

// ================= tensor-core helpers =================
__device__ __forceinline__ uint32_t smem_u32(const void* p) {
    uint32_t a;
    asm("{ .reg .u64 t; cvta.to.shared.u64 t, %1; cvt.u32.u64 %0, t; }" : "=r"(a) : "l"(p));
    return a;
}
__device__ __forceinline__ void cp_async16(uint32_t smem, const void* g) {
    asm volatile("cp.async.cg.shared.global [%0], [%1], 16;" :: "r"(smem), "l"(g));
}
#define CP_COMMIT() asm volatile("cp.async.commit_group;" ::: "memory")
#define CP_WAIT1()  asm volatile("cp.async.wait_group 1;" ::: "memory")
#define CP_WAIT0()  asm volatile("cp.async.wait_group 0;" ::: "memory")

__device__ __forceinline__ void ldmx4(uint32_t* r, uint32_t addr) {
    asm volatile("ldmatrix.sync.aligned.m8n8.x4.shared.b16 {%0,%1,%2,%3}, [%4];"
        : "=r"(r[0]), "=r"(r[1]), "=r"(r[2]), "=r"(r[3]) : "r"(addr));
}
__device__ __forceinline__ void mma16816(float* d, const uint32_t* a, uint32_t b0, uint32_t b1) {
    asm volatile(
        "mma.sync.aligned.m16n8k16.row.col.f32.bf16.bf16.f32 "
        "{%0,%1,%2,%3}, {%4,%5,%6,%7}, {%8,%9}, {%0,%1,%2,%3};"
        : "+f"(d[0]), "+f"(d[1]), "+f"(d[2]), "+f"(d[3])
        : "r"(a[0]), "r"(a[1]), "r"(a[2]), "r"(a[3]), "r"(b0), "r"(b1));
}
__device__ __forceinline__ uint32_t pack_bf2(float x, float y) {
    __nv_bfloat162 t = __floats2bfloat162_rn(x, y);
    return *(uint32_t*)&t;
}
__device__ __forceinline__ unsigned short bfu(__nv_bfloat16 h) {
    return *(unsigned short*)&h;
}

// ---------------- patchify: gather + split bf16 [hi(768)|lo(768)] ----------------
__global__ void patchify_kernel(const float* __restrict__ x, __nv_bfloat16* __restrict__ xs)
{
    int m = blockIdx.x;                 // 0..6271
    int b = m / (NP*NP);
    int p = m % (NP*NP);
    int py = p / NP, px = p % NP;
    for (int i = threadIdx.x; i < IN_DIM; i += blockDim.x) {
        int c = i >> 8;
        int r = (i >> 4) & 15;
        int s = i & 15;
        size_t src = ((size_t)(b*CC + c)*IMG + (py*PS + r))*IMG + (px*PS + s);
        float v = x[src];
        __nv_bfloat16 hi = __float2bfloat16(v);
        __nv_bfloat16 lo = __float2bfloat16(v - __bfloat162float(hi));
        xs[(size_t)m*KA1 + i]      = hi;
        xs[(size_t)m*KA1 + DD + i] = lo;
    }
}

__global__ void cls_init_kernel(const float* __restrict__ cls_emb,
                                const float* __restrict__ pos,
                                float* __restrict__ resid)
{
    int b = blockIdx.x;
    for (int d = threadIdx.x; d < DD; d += blockDim.x)
        resid[(size_t)b*SS*DD + d] = cls_emb[d] + pos[d];
}

// ---------------- weight prep: transpose + bf16 split, stacked K ----------------
__global__ void wprep_kernel(const float* __restrict__ W, __nv_bfloat16* __restrict__ Wp,
                             int K, int N)
{
    __shared__ float t[32][33];
    int l = blockIdx.z;
    const float* Wl = W + (size_t)l*K*N;
    __nv_bfloat16* Wpl = Wp + (size_t)l*N*3*K;
    int n0 = blockIdx.x*32, k0 = blockIdx.y*32;
    int tx = threadIdx.x, ty = threadIdx.y;

    t[ty][tx] = Wl[(size_t)(k0+ty)*N + n0+tx];
    __syncthreads();
    float v = t[tx][ty];
    int row = n0+ty, col = k0+tx;
    __nv_bfloat16 hi = __float2bfloat16(v);
    __nv_bfloat16 lo = __float2bfloat16(v - __bfloat162float(hi));
    __nv_bfloat16* dst = Wpl + (size_t)row*3*K;
    dst[col]       = hi;
    dst[K + col]   = hi;
    dst[2*K + col] = lo;
}

// ---------------- QKV weight prep ----------------
__global__ void qkv_prep_kernel(const float* __restrict__ Wq, const float* __restrict__ Wk,
                                const float* __restrict__ Wv, __nv_bfloat16* __restrict__ wout)
{
    int h = blockIdx.x, mat = blockIdx.y, l = blockIdx.z;
    const float* W = (mat == 0) ? Wq : (mat == 1) ? Wk : Wv;
    const float* Wl = W + (size_t)(l*NH + h)*64*64;
    __nv_bfloat16* dst = wout + (size_t)((l*3 + mat)*NH + h)*64*192;
    for (int idx = threadIdx.x; idx < 4096; idx += 256) {
        int e = idx >> 6, d = idx & 63;
        float v = Wl[e*64 + d];
        __nv_bfloat16 hi = __float2bfloat16(v);
        __nv_bfloat16 lo = __float2bfloat16(v - __bfloat162float(hi));
        dst[e*192 + d]       = hi;
        dst[e*192 + 64 + d]  = hi;
        dst[e*192 + 128 + d] = lo;
    }
}

// ---------------- LayerNorm (192 threads, float4) -> split bf16 [hi|lo] --------
__global__ void ln_kernel(const float* __restrict__ xin, const float* __restrict__ g,
                          const float* __restrict__ bet, __nv_bfloat16* __restrict__ xs)
{
    int row = blockIdx.x;
    int tid = threadIdx.x;                 // 0..191
    const float4* xr = (const float4*)(xin + (size_t)row*DD);
    float4 v = xr[tid];
    float s  = v.x + v.y + v.z + v.w;
    float ss = v.x*v.x + v.y*v.y + v.z*v.z + v.w*v.w;

    __shared__ float rs[6], rss[6], smv[2];
    int lane = tid & 31, w = tid >> 5;
#pragma unroll
    for (int off = 16; off; off >>= 1) {
        s  += __shfl_xor_sync(0xffffffffu, s,  off);
        ss += __shfl_xor_sync(0xffffffffu, ss, off);
    }
    if (lane == 0) { rs[w] = s; rss[w] = ss; }
    __syncthreads();
    if (tid == 0) {
        float S = 0.f, SSq = 0.f;
#pragma unroll
        for (int i = 0; i < 6; i++) { S += rs[i]; SSq += rss[i]; }
        float mean = S * (1.f/768.f);
        float var  = SSq * (1.f/768.f) - mean*mean;
        smv[0] = mean;
        smv[1] = rsqrtf(var + 1e-5f);
    }
    __syncthreads();
    float mean = smv[0], rstd = smv[1];

    float4 gg = ((const float4*)g)[tid];
    float4 bb = ((const float4*)bet)[tid];
    float y0 = (v.x - mean)*rstd*gg.x + bb.x;
    float y1 = (v.y - mean)*rstd*gg.y + bb.y;
    float y2 = (v.z - mean)*rstd*gg.z + bb.z;
    float y3 = (v.w - mean)*rstd*gg.w + bb.w;
    __nv_bfloat16 h0 = __float2bfloat16(y0);
    __nv_bfloat16 h1 = __float2bfloat16(y1);
    __nv_bfloat16 h2 = __float2bfloat16(y2);
    __nv_bfloat16 h3 = __float2bfloat16(y3);
    uint32_t hi01 = (uint32_t)bfu(h0) | ((uint32_t)bfu(h1) << 16);
    uint32_t hi23 = (uint32_t)bfu(h2) | ((uint32_t)bfu(h3) << 16);
    uint32_t lo01 = pack_bf2(y0 - __bfloat162float(h0), y1 - __bfloat162float(h1));
    uint32_t lo23 = pack_bf2(y2 - __bfloat162float(h2), y3 - __bfloat162float(h3));
    __nv_bfloat16* dst = xs + (size_t)row*KA1;
    *(uint2*)(dst + tid*4)      = make_uint2(hi01, hi23);
    *(uint2*)(dst + DD + tid*4) = make_uint2(lo01, lo23);
}

// ---------------- HMMA GEMM, 128x128 tile (GEMM1 + embed) ----------------
template<int MODE>
__global__ void __launch_bounds__(256, 2)
mma_mlp_kernel(const __nv_bfloat16* __restrict__ A, const __nv_bfloat16* __restrict__ Bw,
               const float* __restrict__ bias, __nv_bfloat16* __restrict__ hs_out,
               float* __restrict__ resid, int nk, int strideA, int strideB,
               const float* __restrict__ extra)
{
    extern __shared__ char smc[];
    const uint32_t sbase = smem_u32(smc);
    const int tid = threadIdx.x;
    const int wid = tid >> 5, lane = tid & 31;
    const int wm = wid & 1, wn = wid >> 1;
    const int bx = blockIdx.x, by = blockIdx.y;
    const int NC = 3*nk;

    const __nv_bfloat16* Abase = A + (size_t)(by*128)*strideA;
    const __nv_bfloat16* Bbase = Bw + (size_t)(bx*128)*strideB;

    float acc[4][4][4];
#pragma unroll
    for (int i = 0; i < 4; i++)
#pragma unroll
        for (int j = 0; j < 4; j++)
#pragma unroll
            for (int q = 0; q < 4; q++) acc[i][j][q] = 0.f;

    const int lq = tid & 7;
    const int lr = tid >> 3;

    auto load_chunk = [&](int c, int p) {
        int cwrap = (c < 2*nk) ? c : (c - 2*nk);
        const __nv_bfloat16* Ap = Abase + (size_t)cwrap*64;
        const __nv_bfloat16* Bp = Bbase + (size_t)c*64;
        uint32_t sA = sbase + p*32768;
        uint32_t sB = sA + 16384;
#pragma unroll
        for (int i = 0; i < 4; i++) {
            int r = i*32 + lr;
            uint32_t off = r*128 + lq*16;
            uint32_t sw = off ^ ((off >> 3) & 0x70);
            cp_async16(sA + sw, Ap + (size_t)r*strideA + lq*8);
            cp_async16(sB + sw, Bp + (size_t)r*strideB + lq*8);
        }
        CP_COMMIT();
    };

    const int l15 = lane & 15;
    const int lks = (lane >> 4) * 16;

    load_chunk(0, 0);

    for (int c = 0; c < NC; c++) {
        int p = c & 1;
        if (c + 1 < NC) { load_chunk(c+1, (c+1)&1); CP_WAIT1(); }
        else            { CP_WAIT0(); }
        __syncthreads();

        uint32_t sA = sbase + p*32768;
        uint32_t sB = sA + 16384;
#pragma unroll
        for (int ks = 0; ks < 4; ks++) {
            uint32_t b0[4], b1[4];
            {
                uint32_t off = (wn*32 + l15)*128 + ks*32 + lks;
                ldmx4(b0, sB + (off ^ ((off >> 3) & 0x70)));
                off = (wn*32 + 16 + l15)*128 + ks*32 + lks;
                ldmx4(b1, sB + (off ^ ((off >> 3) & 0x70)));
            }
#pragma unroll
            for (int mt = 0; mt < 4; mt++) {
                uint32_t a[4];
                uint32_t off = (wm*64 + mt*16 + l15)*128 + ks*32 + lks;
                ldmx4(a, sA + (off ^ ((off >> 3) & 0x70)));
                mma16816(acc[mt][0], a, b0[0], b0[2]);
                mma16816(acc[mt][1], a, b0[1], b0[3]);
                mma16816(acc[mt][2], a, b1[0], b1[2]);
                mma16816(acc[mt][3], a, b1[1], b1[3]);
            }
        }
        __syncthreads();
    }

    const int gm0 = by*128 + wm*64 + (lane >> 2);
    const int gn0 = bx*128 + wn*32 + (lane & 3)*2;

#pragma unroll
    for (int mt = 0; mt < 4; mt++) {
#pragma unroll
        for (int nt = 0; nt < 4; nt++) {
            int col = gn0 + nt*8;
            float bi0 = bias[col], bi1 = bias[col+1];
            int r0 = gm0 + mt*16;
            int r1 = r0 + 8;
            float v00 = acc[mt][nt][0] + bi0;
            float v01 = acc[mt][nt][1] + bi1;
            float v10 = acc[mt][nt][2] + bi0;
            float v11 = acc[mt][nt][3] + bi1;
            if (MODE == 0) {
                float g00 = 0.5f*v00*(1.f + erff(v00*0.70710678118654752f));
                float g01 = 0.5f*v01*(1.f + erff(v01*0.70710678118654752f));
                float g10 = 0.5f*v10*(1.f + erff(v10*0.70710678118654752f));
                float g11 = 0.5f*v11*(1.f + erff(v11*0.70710678118654752f));
                __nv_bfloat16 h00 = __float2bfloat16(g00);
                __nv_bfloat16 h01 = __float2bfloat16(g01);
                __nv_bfloat16 h10 = __float2bfloat16(g10);
                __nv_bfloat16 h11 = __float2bfloat16(g11);
                uint32_t hi0 = (uint32_t)bfu(h00) | ((uint32_t)bfu(h01) << 16);
                uint32_t hi1 = (uint32_t)bfu(h10) | ((uint32_t)bfu(h11) << 16);
                uint32_t lo0 = pack_bf2(g00 - __bfloat162float(h00), g01 - __bfloat162float(h01));
                uint32_t lo1 = pack_bf2(g10 - __bfloat162float(h10), g11 - __bfloat162float(h11));
                if (r0 < NTOK) {
                    *(uint32_t*)(hs_out + (size_t)r0*KA2 + col)        = hi0;
                    *(uint32_t*)(hs_out + (size_t)r0*KA2 + MLPD + col) = lo0;
                }
                if (r1 < NTOK) {
                    *(uint32_t*)(hs_out + (size_t)r1*KA2 + col)        = hi1;
                    *(uint32_t*)(hs_out + (size_t)r1*KA2 + MLPD + col) = lo1;
                }
            } else { // MODE 2: embed epilogue
                {
                    int pp = r0 % (NP*NP), bb = r0 / (NP*NP);
                    int orow = bb*SS + 1 + pp;
                    float2* p = (float2*)(resid + (size_t)orow*DD + col);
                    const float2* e = (const float2*)(extra + (size_t)(pp+1)*DD + col);
                    float2 ev = *e;
                    *p = make_float2(v00 + ev.x, v01 + ev.y);
                }
                {
                    int pp = r1 % (NP*NP), bb = r1 / (NP*NP);
                    int orow = bb*SS + 1 + pp;
                    float2* p = (float2*)(resid + (size_t)orow*DD + col);
                    const float2* e = (const float2*)(extra + (size_t)(pp+1)*DD + col);
                    float2 ev = *e;
                    *p = make_float2(v10 + ev.x, v11 + ev.y);
                }
            }
        }
    }
}

// ---------------- HMMA GEMM2: 128x64 tiles, occ 3 ----------
__global__ void __launch_bounds__(256, 3)
mma_g2_kernel(const __nv_bfloat16* __restrict__ A, const __nv_bfloat16* __restrict__ Bw,
              const float* __restrict__ bias, float* __restrict__ resid,
              int nk, int strideA, int strideB)
{
    extern __shared__ char smc[];
    const uint32_t sbase = smem_u32(smc);
    const int tid = threadIdx.x;
    const int wid = tid >> 5, lane = tid & 31;
    const int wm = wid & 3, wn = wid >> 2;
    const int bx = blockIdx.x, by = blockIdx.y;
    const int NC = 3*nk;

    const __nv_bfloat16* Abase = A + (size_t)(by*128)*strideA;
    const __nv_bfloat16* Bbase = Bw + (size_t)(bx*64)*strideB;

    float acc[2][4][4];
#pragma unroll
    for (int i = 0; i < 2; i++)
#pragma unroll
        for (int j = 0; j < 4; j++)
#pragma unroll
            for (int q = 0; q < 4; q++) acc[i][j][q] = 0.f;

    const int lq = tid & 7;
    const int lr = tid >> 3;

    auto load_chunk = [&](int c, int p) {
        int cwrap = (c < 2*nk) ? c : (c - 2*nk);
        const __nv_bfloat16* Ap = Abase + (size_t)cwrap*64;
        const __nv_bfloat16* Bp = Bbase + (size_t)c*64;
        uint32_t sA = sbase + p*24576;
        uint32_t sB = sA + 16384;
#pragma unroll
        for (int i = 0; i < 4; i++) {
            int r = i*32 + lr;
            uint32_t off = r*128 + lq*16;
            uint32_t sw = off ^ ((off >> 3) & 0x70);
            cp_async16(sA + sw, Ap + (size_t)r*strideA + lq*8);
        }
#pragma unroll
        for (int i = 0; i < 2; i++) {
            int r = i*32 + lr;
            uint32_t off = r*128 + lq*16;
            uint32_t sw = off ^ ((off >> 3) & 0x70);
            cp_async16(sB + sw, Bp + (size_t)r*strideB + lq*8);
        }
        CP_COMMIT();
    };

    const int l15 = lane & 15;
    const int lks = (lane >> 4) * 16;

    load_chunk(0, 0);

    for (int c = 0; c < NC; c++) {
        int p = c & 1;
        if (c + 1 < NC) { load_chunk(c+1, (c+1)&1); CP_WAIT1(); }
        else            { CP_WAIT0(); }
        __syncthreads();

        uint32_t sA = sbase + p*24576;
        uint32_t sB = sA + 16384;
#pragma unroll
        for (int ks = 0; ks < 4; ks++) {
            uint32_t b0[4], b1[4];
            {
                uint32_t off = (wn*32 + l15)*128 + ks*32 + lks;
                ldmx4(b0, sB + (off ^ ((off >> 3) & 0x70)));
                off = (wn*32 + 16 + l15)*128 + ks*32 + lks;
                ldmx4(b1, sB + (off ^ ((off >> 3) & 0x70)));
            }
#pragma unroll
            for (int mt = 0; mt < 2; mt++) {
                uint32_t a[4];
                uint32_t off = (wm*32 + mt*16 + l15)*128 + ks*32 + lks;
                ldmx4(a, sA + (off ^ ((off >> 3) & 0x70)));
                mma16816(acc[mt][0], a, b0[0], b0[2]);
                mma16816(acc[mt][1], a, b0[1], b0[3]);
                mma16816(acc[mt][2], a, b1[0], b1[2]);
                mma16816(acc[mt][3], a, b1[1], b1[3]);
            }
        }
        __syncthreads();
    }

    const int gm0 = by*128 + wm*32 + (lane >> 2);
    const int gn0 = bx*64 + wn*32 + (lane & 3)*2;

#pragma unroll
    for (int mt = 0; mt < 2; mt++) {
#pragma unroll
        for (int nt = 0; nt < 4; nt++) {
            int col = gn0 + nt*8;
            float bi0 = bias[col], bi1 = bias[col+1];
            int r0 = gm0 + mt*16;
            int r1 = r0 + 8;
            if (r0 < NTOK) {
                float2* p = (float2*)(resid + (size_t)r0*DD + col);
                float2 t = *p;
                t.x += acc[mt][nt][0] + bi0;
                t.y += acc[mt][nt][1] + bi1;
                *p = t;
            }
            if (r1 < NTOK) {
                float2* p = (float2*)(resid + (size_t)r1*DD + col);
                float2 t = *p;
                t.x += acc[mt][nt][2] + bi0;
                t.y += acc[mt][nt][3] + bi1;
                *p = t;
            }
        }
    }
}

// ---------------- HMMA QKV projection: q/k 2-section [hi|lo], v transposed ----
__global__ void __launch_bounds__(128, 3)
qkv_mma_kernel(const __nv_bfloat16* __restrict__ xs, const __nv_bfloat16* __restrict__ wqkv,
               const float* __restrict__ bq, const float* __restrict__ bk,
               const float* __restrict__ bv,
               __nv_bfloat16* __restrict__ qsd, __nv_bfloat16* __restrict__ ksd,
               __nv_bfloat16* __restrict__ vtd)
{
    extern __shared__ char smc[];
    const uint32_t sbase = smem_u32(smc);
    const int tid = threadIdx.x;
    const int wid = tid >> 5, lane = tid & 31;
    const int hm = blockIdx.x;
    const int mat = hm / NH, h = hm % NH;
    const int by = blockIdx.y;

    const __nv_bfloat16* Wp = wqkv + (size_t)hm*64*192;
    const float* bias = (mat == 0) ? bq : (mat == 1) ? bk : bv;

    const int lq = tid & 7, lr = tid >> 3;
#pragma unroll
    for (int c = 0; c < 2; c++) {
        const __nv_bfloat16* Ap = xs + (c ? (DD + h*64) : (h*64));
#pragma unroll
        for (int i = 0; i < 8; i++) {
            int r = i*16 + lr;
            uint32_t off = r*128 + lq*16;
            uint32_t sw = off ^ ((off >> 3) & 0x70);
            cp_async16(sbase + c*16384 + sw, Ap + (size_t)(by*128 + r)*KA1 + lq*8);
        }
    }
#pragma unroll
    for (int c = 0; c < 3; c++) {
#pragma unroll
        for (int i = 0; i < 4; i++) {
            int r = i*16 + lr;
            uint32_t off = r*128 + lq*16;
            uint32_t sw = off ^ ((off >> 3) & 0x70);
            cp_async16(sbase + 32768 + c*8192 + sw, Wp + (size_t)r*192 + c*64 + lq*8);
        }
    }
    CP_COMMIT();
    CP_WAIT0();
    __syncthreads();

    float acc[2][8][4];
#pragma unroll
    for (int i = 0; i < 2; i++)
#pragma unroll
        for (int j = 0; j < 8; j++)
#pragma unroll
            for (int t = 0; t < 4; t++) acc[i][j][t] = 0.f;

    const int l15 = lane & 15;
    const int lks = (lane >> 4) * 16;
    const int m0 = wid*32;

#pragma unroll
    for (int pass = 0; pass < 3; pass++) {
        uint32_t sA = sbase + ((pass == 1) ? 16384 : 0);
        uint32_t sB = sbase + 32768 + pass*8192;
#pragma unroll
        for (int ks = 0; ks < 4; ks++) {
            uint32_t b[4][4];
#pragma unroll
            for (int nb = 0; nb < 4; nb++) {
                uint32_t off = (nb*16 + l15)*128 + ks*32 + lks;
                ldmx4(b[nb], sB + (off ^ ((off >> 3) & 0x70)));
            }
#pragma unroll
            for (int mt = 0; mt < 2; mt++) {
                uint32_t a[4];
                uint32_t off = (m0 + mt*16 + l15)*128 + ks*32 + lks;
                ldmx4(a, sA + (off ^ ((off >> 3) & 0x70)));
#pragma unroll
                for (int nb = 0; nb < 4; nb++) {
                    mma16816(acc[mt][2*nb],   a, b[nb][0], b[nb][2]);
                    mma16816(acc[mt][2*nb+1], a, b[nb][1], b[nb][3]);
                }
            }
        }
    }

    const int c0 = (lane & 3)*2;
#pragma unroll
    for (int mt = 0; mt < 2; mt++) {
#pragma unroll
        for (int nt = 0; nt < 8; nt++) {
            int e = nt*8 + c0;
            float bi0 = bias[h*64 + e], bi1 = bias[h*64 + e + 1];
            int r0 = by*128 + m0 + mt*16 + (lane >> 2);
#pragma unroll
            for (int half = 0; half < 2; half++) {
                int r = r0 + half*8;
                if (r >= NTOK) continue;
                float v0 = acc[mt][nt][2*half]   + bi0;
                float v1 = acc[mt][nt][2*half+1] + bi1;
                __nv_bfloat16 h0 = __float2bfloat16(v0);
                __nv_bfloat16 h1 = __float2bfloat16(v1);
                float l0 = v0 - __bfloat162float(h0);
                float l1 = v1 - __bfloat162float(h1);
                int b = r / SS, s = r % SS;
                int bh = b*NH + h;
                if (mat == 2) {
                    __nv_bfloat16* vb = vtd + (size_t)bh*128*VTP;
                    vb[(size_t)e*VTP + s]          = h0;
                    vb[(size_t)(e+1)*VTP + s]      = h1;
                    vb[(size_t)(64+e)*VTP + s]     = __float2bfloat16(l0);
                    vb[(size_t)(64+e+1)*VTP + s]   = __float2bfloat16(l1);
                } else {
                    uint32_t hi = (uint32_t)bfu(h0) | ((uint32_t)bfu(h1) << 16);
                    uint32_t lo = pack_bf2(l0, l1);
                    __nv_bfloat16* base = (mat == 0 ? qsd : ksd) + ((size_t)bh*SPAD + s)*128;
                    *(uint32_t*)(base + e)      = hi;
                    *(uint32_t*)(base + 64 + e) = lo;
                }
            }
        }
    }
}

// ---------------- HMMA fused attention: dual-plane Q/K (128B rows) -------------
#define AK_PLANE 26624     // 208*128
__global__ void __launch_bounds__(256, 1)
attn_mma_kernel(const __nv_bfloat16* __restrict__ qsd, const __nv_bfloat16* __restrict__ ksd,
                const __nv_bfloat16* __restrict__ vtd, float* __restrict__ resid)
{
    extern __shared__ char smc[];
    const uint32_t sbase = smem_u32(smc);
    const uint32_t sQ = sbase;                         // 2 planes x 16384
    const uint32_t sK = sbase + 32768;                 // 2 planes x 26624
    const uint32_t sV = sbase + 32768 + 2*AK_PLANE;    // 128 x 464

    const int tid = threadIdx.x;
    const int wid = tid >> 5, lane = tid & 31;
    const int qt = blockIdx.x, bh = blockIdx.y;
    const int b = bh / NH, h = bh % NH;

    const __nv_bfloat16* Qg = qsd + ((size_t)bh*SPAD + (size_t)qt*128)*128;
    const __nv_bfloat16* Kg = ksd + (size_t)bh*SPAD*128;
    const __nv_bfloat16* Vg = vtd + (size_t)bh*128*VTP;

    // group 0: Q + K (global rows are 256B = [hi 128B | lo 128B] -> two planes)
    for (int i = tid; i < 128*16; i += 256) {
        int r = i >> 4, c = i & 15;
        uint32_t pl = (c < 8) ? 0u : 16384u;
        uint32_t off = r*128 + (c & 7)*16;
        cp_async16(sQ + pl + (off ^ ((off >> 3) & 0x70)), Qg + (size_t)r*128 + c*8);
    }
    for (int i = tid; i < SPAD*16; i += 256) {
        int r = i >> 4, c = i & 15;
        uint32_t pl = (c < 8) ? 0u : (uint32_t)AK_PLANE;
        uint32_t off = r*128 + (c & 7)*16;
        cp_async16(sK + pl + (off ^ ((off >> 3) & 0x70)), Kg + (size_t)r*128 + c*8);
    }
    CP_COMMIT();
    // group 1: V^T
    for (int i = tid; i < 128*29; i += 256) {
        int r = i / 29, c = i % 29;
        cp_async16(sV + r*464 + c*16, Vg + (size_t)r*VTP + c*8);
    }
    CP_COMMIT();
    CP_WAIT1();
    __syncthreads();

    float s[26][4];
#pragma unroll
    for (int t = 0; t < 26; t++)
#pragma unroll
        for (int e = 0; e < 4; e++) s[t][e] = 0.f;

    const int l15 = lane & 15;
    const int lks = (lane >> 4) * 16;
    const int m0 = wid * 16;

    // stacked K=192: kc0-3 Qh*Kh, kc4-7 Ql*Kh, kc8-11 Qh*Kl
#pragma unroll 1
    for (int kc = 0; kc < 12; kc++) {
        uint32_t qpl = (kc >= 4 && kc < 8) ? 16384u : 0u;
        uint32_t kpl = (kc >= 8) ? (uint32_t)AK_PLANE : 0u;
        int cb = (kc & 3)*32;
        uint32_t a[4];
        uint32_t off = (m0 + l15)*128 + cb + lks;
        ldmx4(a, sQ + qpl + (off ^ ((off >> 3) & 0x70)));
#pragma unroll
        for (int nb = 0; nb < 13; nb++) {
            uint32_t bb[4];
            off = (nb*16 + l15)*128 + cb + lks;
            ldmx4(bb, sK + kpl + (off ^ ((off >> 3) & 0x70)));
            mma16816(s[2*nb],   a, bb[0], bb[2]);
            mma16816(s[2*nb+1], a, bb[1], bb[3]);
        }
    }

    const int c0 = 2*(lane & 3);
    float mx0 = -1e30f, mx1 = -1e30f;
#pragma unroll
    for (int t = 0; t < 26; t++) {
        int j0 = t*8 + c0;
        float v0 = (j0   < SS) ? s[t][0]*0.125f : -1e30f;
        float v1 = (j0+1 < SS) ? s[t][1]*0.125f : -1e30f;
        float v2 = (j0   < SS) ? s[t][2]*0.125f : -1e30f;
        float v3 = (j0+1 < SS) ? s[t][3]*0.125f : -1e30f;
        s[t][0] = v0; s[t][1] = v1; s[t][2] = v2; s[t][3] = v3;
        mx0 = fmaxf(mx0, fmaxf(v0, v1));
        mx1 = fmaxf(mx1, fmaxf(v2, v3));
    }
    mx0 = fmaxf(mx0, __shfl_xor_sync(0xffffffffu, mx0, 1));
    mx0 = fmaxf(mx0, __shfl_xor_sync(0xffffffffu, mx0, 2));
    mx1 = fmaxf(mx1, __shfl_xor_sync(0xffffffffu, mx1, 1));
    mx1 = fmaxf(mx1, __shfl_xor_sync(0xffffffffu, mx1, 2));

    float sum0 = 0.f, sum1 = 0.f;
#pragma unroll
    for (int t = 0; t < 26; t++) {
        float p0 = __expf(s[t][0] - mx0);
        float p1 = __expf(s[t][1] - mx0);
        float p2 = __expf(s[t][2] - mx1);
        float p3 = __expf(s[t][3] - mx1);
        s[t][0] = p0; s[t][1] = p1; s[t][2] = p2; s[t][3] = p3;
        sum0 += p0 + p1;
        sum1 += p2 + p3;
    }
    sum0 += __shfl_xor_sync(0xffffffffu, sum0, 1);
    sum0 += __shfl_xor_sync(0xffffffffu, sum0, 2);
    sum1 += __shfl_xor_sync(0xffffffffu, sum1, 1);
    sum1 += __shfl_xor_sync(0xffffffffu, sum1, 2);
    float inv0 = 1.f / sum0, inv1 = 1.f / sum1;

    CP_WAIT0();
    __syncthreads();

    float o[8][4];
#pragma unroll
    for (int t = 0; t < 8; t++)
#pragma unroll
        for (int e = 0; e < 4; e++) o[t][e] = 0.f;

#pragma unroll 1
    for (int kt = 0; kt < 13; kt++) {
        uint32_t ah[4], al[4];
        {
            float p00 = s[2*kt][0],   p01 = s[2*kt][1],   p02 = s[2*kt][2],   p03 = s[2*kt][3];
            float p10 = s[2*kt+1][0], p11 = s[2*kt+1][1], p12 = s[2*kt+1][2], p13 = s[2*kt+1][3];
            __nv_bfloat16 h00 = __float2bfloat16(p00), h01 = __float2bfloat16(p01);
            __nv_bfloat16 h02 = __float2bfloat16(p02), h03 = __float2bfloat16(p03);
            __nv_bfloat16 h10 = __float2bfloat16(p10), h11 = __float2bfloat16(p11);
            __nv_bfloat16 h12 = __float2bfloat16(p12), h13 = __float2bfloat16(p13);
            ah[0] = (uint32_t)bfu(h00) | ((uint32_t)bfu(h01) << 16);
            ah[1] = (uint32_t)bfu(h02) | ((uint32_t)bfu(h03) << 16);
            ah[2] = (uint32_t)bfu(h10) | ((uint32_t)bfu(h11) << 16);
            ah[3] = (uint32_t)bfu(h12) | ((uint32_t)bfu(h13) << 16);
            al[0] = pack_bf2(p00 - __bfloat162float(h00), p01 - __bfloat162float(h01));
            al[1] = pack_bf2(p02 - __bfloat162float(h02), p03 - __bfloat162float(h03));
            al[2] = pack_bf2(p10 - __bfloat162float(h10), p11 - __bfloat162float(h11));
            al[3] = pack_bf2(p12 - __bfloat162float(h12), p13 - __bfloat162float(h13));
        }
#pragma unroll
        for (int nb = 0; nb < 4; nb++) {
            uint32_t bh_[4], bl_[4];
            ldmx4(bh_, sV + (nb*16 + l15)*464 + kt*32 + lks);
            ldmx4(bl_, sV + (64 + nb*16 + l15)*464 + kt*32 + lks);
            mma16816(o[2*nb],   ah, bh_[0], bh_[2]);
            mma16816(o[2*nb+1], ah, bh_[1], bh_[3]);
            mma16816(o[2*nb],   al, bh_[0], bh_[2]);
            mma16816(o[2*nb+1], al, bh_[1], bh_[3]);
            mma16816(o[2*nb],   ah, bl_[0], bl_[2]);
            mma16816(o[2*nb+1], ah, bl_[1], bl_[3]);
        }
    }

    const int r0 = qt*128 + m0 + (lane >> 2);
    const int r1 = r0 + 8;
#pragma unroll
    for (int nb = 0; nb < 8; nb++) {
        int col = h*64 + nb*8 + c0;
        if (r0 < SS) {
            float2* p = (float2*)(resid + ((size_t)(b*SS + r0))*DD + col);
            float2 t = *p;
            t.x += o[nb][0]*inv0;
            t.y += o[nb][1]*inv0;
            *p = t;
        }
        if (r1 < SS) {
            float2* p = (float2*)(resid + ((size_t)(b*SS + r1))*DD + col);
            float2 t = *p;
            t.x += o[nb][2]*inv1;
            t.y += o[nb][3]*inv1;
            *p = t;
        }
    }
}

// ---------------- classifier head ----------------
__global__ void head_kernel(const float* __restrict__ resid, const float* __restrict__ Wc,
                            const float* __restrict__ bc, float* __restrict__ out)
{
    __shared__ float sx[768];
    __shared__ float logit[1000];
    __shared__ float red[8];
    __shared__ float bscalar;

    int b = blockIdx.x;
    int tid = threadIdx.x;
    int lane = tid & 31, w = tid >> 5;

    for (int i = tid; i < 768; i += 256) sx[i] = resid[(size_t)b*SS*DD + i];
    __syncthreads();

    for (int o = tid; o < OUTC; o += 256) {
        float acc = bc[o];
        for (int kk = 0; kk < 768; kk++) acc += sx[kk]*Wc[(size_t)kk*OUTC + o];
        logit[o] = acc;
    }
    __syncthreads();

    float m = -1e30f;
    for (int o = tid; o < OUTC; o += 256) m = fmaxf(m, logit[o]);
#pragma unroll
    for (int off = 16; off; off >>= 1) m = fmaxf(m, __shfl_xor_sync(0xffffffffu, m, off));
    if (lane == 0) red[w] = m;
    __syncthreads();
    if (tid == 0) {
        float mm = red[0];
#pragma unroll
        for (int i = 1; i < 8; i++) mm = fmaxf(mm, red[i]);
        bscalar = mm;
    }
    __syncthreads();
    m = bscalar;

    float s = 0.f;
    for (int o = tid; o < OUTC; o += 256) {
        float e = __expf(logit[o] - m);
        logit[o] = e;
        s += e;
    }
#pragma unroll
    for (int off = 16; off; off >>= 1) s += __shfl_xor_sync(0xffffffffu, s, off);
    if (lane == 0) red[w] = s;
    __syncthreads();
    if (tid == 0) {
        float ssum = 0.f;
#pragma unroll
        for (int i = 0; i < 8; i++) ssum += red[i];
        bscalar = 1.f / ssum;
    }
    __syncthreads();
    float invs = bscalar;
    for (int o = tid; o < OUTC; o += 256)
        out[(size_t)b*OUTC + o] = logit[o] * invs;
}

// ---------------- launcher ----------------
extern "C" void kernel_launch(void* const* d_in, const int* in_sizes, int n_in,
                              void* d_out, int out_size)
{
    const float* x       = (const float*)d_in[0];
    const float* cls_emb = (const float*)d_in[1];
    const float* pos     = (const float*)d_in[2];
    const float* Wmap    = (const float*)d_in[3];
    const float* bmap    = (const float*)d_in[4];
    const float* ln1_g   = (const float*)d_in[5];
    const float* ln1_b   = (const float*)d_in[6];
    const float* Wq      = (const float*)d_in[7];
    const float* bq      = (const float*)d_in[8];
    const float* Wk      = (const float*)d_in[9];
    const float* bk      = (const float*)d_in[10];
    const float* Wv      = (const float*)d_in[11];
    const float* bv      = (const float*)d_in[12];
    const float* ln2_g   = (const float*)d_in[13];
    const float* ln2_b   = (const float*)d_in[14];
    const float* W1      = (const float*)d_in[15];
    const float* b1      = (const float*)d_in[16];
    const float* W2      = (const float*)d_in[17];
    const float* b2      = (const float*)d_in[18];
    const float* Wc      = (const float*)d_in[19];
    const float* bc      = (const float*)d_in[20];
    float* out = (float*)d_out;

    float *resid;
    __nv_bfloat16 *xs, *hs, *w1p, *w2p, *wmapp, *wqkv, *qsd, *ksd, *vtd;
    cudaGetSymbolAddress((void**)&resid, g_resid);
    cudaGetSymbolAddress((void**)&xs,    g_xs);
    cudaGetSymbolAddress((void**)&hs,    g_hs);
    cudaGetSymbolAddress((void**)&w1p,   g_w1p);
    cudaGetSymbolAddress((void**)&w2p,   g_w2p);
    cudaGetSymbolAddress((void**)&wmapp, g_wmapp);
    cudaGetSymbolAddress((void**)&wqkv,  g_wqkv);
    cudaGetSymbolAddress((void**)&qsd,   g_qs);
    cudaGetSymbolAddress((void**)&ksd,   g_ks);
    cudaGetSymbolAddress((void**)&vtd,   g_vt);

    const int MMA_SMEM  = 65536;
    const int G2_SMEM   = 49152;
    const int QKV_SMEM  = 2*16384 + 3*8192;             // 57,344 B
    const int ATTN_SMEM = 32768 + 2*AK_PLANE + 128*464; // 145,408 B
    cudaFuncSetAttribute(mma_mlp_kernel<0>, cudaFuncAttributeMaxDynamicSharedMemorySize, MMA_SMEM);
    cudaFuncSetAttribute(mma_mlp_kernel<2>, cudaFuncAttributeMaxDynamicSharedMemorySize, MMA_SMEM);
    cudaFuncSetAttribute(mma_g2_kernel, cudaFuncAttributeMaxDynamicSharedMemorySize, G2_SMEM);
    cudaFuncSetAttribute(qkv_mma_kernel, cudaFuncAttributeMaxDynamicSharedMemorySize, QKV_SMEM);
    cudaFuncSetAttribute(attn_mma_kernel, cudaFuncAttributeMaxDynamicSharedMemorySize, ATTN_SMEM);

    // weight prep
    wprep_kernel<<<dim3(MLPD/32, DD/32, LL), dim3(32,32)>>>(W1, w1p, DD, MLPD);
    wprep_kernel<<<dim3(DD/32, MLPD/32, LL), dim3(32,32)>>>(W2, w2p, MLPD, DD);
    wprep_kernel<<<dim3(DD/32, IN_DIM/32, 1), dim3(32,32)>>>(Wmap, wmapp, IN_DIM, DD);
    qkv_prep_kernel<<<dim3(NH, 3, LL), 256>>>(Wq, Wk, Wv, wqkv);

    // patch embed (split bf16 -> HMMA) + positional
    patchify_kernel<<<NPATCH, 256>>>(x, xs);
    mma_mlp_kernel<2><<<dim3(DD/128, NPATCH/128), 256, MMA_SMEM>>>(
        xs, wmapp, bmap, nullptr, resid, 12, KA1, KB1, pos);
    cls_init_kernel<<<BB, 256>>>(cls_emb, pos, resid);

    for (int l = 0; l < LL; l++) {
        ln_kernel<<<NTOK, 192>>>(resid, ln1_g + (size_t)l*DD, ln1_b + (size_t)l*DD, xs);
        qkv_mma_kernel<<<dim3(3*NH, MPAD/128), 128, QKV_SMEM>>>(
            xs, wqkv + (size_t)l*3*NH*64*192,
            bq + (size_t)l*NH*DH, bk + (size_t)l*NH*DH, bv + (size_t)l*NH*DH,
            qsd, ksd, vtd);
        attn_mma_kernel<<<dim3(2, BB*NH), 256, ATTN_SMEM>>>(qsd, ksd, vtd, resid);

        ln_kernel<<<NTOK, 192>>>(resid, ln2_g + (size_t)l*DD, ln2_b + (size_t)l*DD, xs);
        mma_mlp_kernel<0><<<dim3(MLPD/128, MPAD/128), 256, MMA_SMEM>>>(
            xs, w1p + (size_t)l*MLPD*KB1, b1 + (size_t)l*MLPD, hs, nullptr, 12, KA1, KB1, nullptr);
        mma_g2_kernel<<<dim3(DD/64, MPAD/128), 256, G2_SMEM>>>(
            hs, w2p + (size_t)l*DD*KB2, b2 + (size_t)l*DD, resid, 48, KA2, KB2);
    }

    head_kernel<<<BB, 256>>>(resid, Wc, bc, out);
}

// round 15
// speedup vs baseline: 1.5533x; 1.0266x over previous
#include <cuda_runtime.h>
#include <cuda_bf16.h>
#include <math.h>
#include <stdint.h>

// ---------------- problem constants ----------------
#define BB      32
#define CC      3
#define IMG     224
#define NP      14
#define PS      16
#define IN_DIM  768
#define DD      768
#define NH      12
#define DH      64
#define LL      12
#define MLPD    3072
#define OUTC    1000
#define SS      197          // NP*NP + 1
#define NTOK    (BB*SS)      // 6304
#define NPATCH  (BB*NP*NP)   // 6272
#define MPAD    6400         // NTOK padded to 50*128

#define KA1     (2*DD)       // 1536: [hi|lo]
#define KA2     (2*MLPD)     // 6144

#define SPAD    208          // padded seq len for attention tiles
#define VTP     232          // V^T row pitch (elems)

// ---------------- scratch (device globals; no runtime alloc) ----------------
static __device__ float g_resid[NTOK*DD];
static __device__ float g_logit[BB*OUTC];
static __device__ __nv_bfloat16 g_xs[(size_t)MPAD*KA1];
static __device__ __nv_bfloat16 g_hs[(size_t)MPAD*KA2];
static __device__ __nv_bfloat16 g_w1p[(size_t)LL*MLPD*KA1];
static __device__ __nv_bfloat16 g_w2p[(size_t)LL*DD*KA2];
static __device__ __nv_bfloat16 g_wmapp[(size_t)DD*KA1];
static __device__ __nv_bfloat16 g_wqkv[(size_t)LL*3*NH*64*192];
static __device__ __nv_bfloat16 g_qs[(size_t)BB*NH*SPAD*128 + 128*128]; // [bh][s][qh|ql] +pad
static __device__ __nv_bfloat16 g_ks[(size_t)BB*NH*SPAD*128];           // [bh][s][kh|kl]
static __device__ __nv_bfloat16 g_vt[(size_t)BB*NH*128*VTP];

// ================= tensor-core helpers =================
__device__ __forceinline__ uint32_t smem_u32(const void* p) {
    uint32_t a;
    asm("{ .reg .u64 t; cvta.to.shared.u64 t, %1; cvt.u32.u64 %0, t; }" : "=r"(a) : "l"(p));
    return a;
}
__device__ __forceinline__ void cp_async16(uint32_t smem, const void* g) {
    asm volatile("cp.async.cg.shared.global [%0], [%1], 16;" :: "r"(smem), "l"(g));
}
#define CP_COMMIT() asm volatile("cp.async.commit_group;" ::: "memory")
#define CP_WAIT1()  asm volatile("cp.async.wait_group 1;" ::: "memory")
#define CP_WAIT0()  asm volatile("cp.async.wait_group 0;" ::: "memory")

__device__ __forceinline__ void ldmx4(uint32_t* r, uint32_t addr) {
    asm volatile("ldmatrix.sync.aligned.m8n8.x4.shared.b16 {%0,%1,%2,%3}, [%4];"
        : "=r"(r[0]), "=r"(r[1]), "=r"(r[2]), "=r"(r[3]) : "r"(addr));
}
__device__ __forceinline__ void mma16816(float* d, const uint32_t* a, uint32_t b0, uint32_t b1) {
    asm volatile(
        "mma.sync.aligned.m16n8k16.row.col.f32.bf16.bf16.f32 "
        "{%0,%1,%2,%3}, {%4,%5,%6,%7}, {%8,%9}, {%0,%1,%2,%3};"
        : "+f"(d[0]), "+f"(d[1]), "+f"(d[2]), "+f"(d[3])
        : "r"(a[0]), "r"(a[1]), "r"(a[2]), "r"(a[3]), "r"(b0), "r"(b1));
}
__device__ __forceinline__ uint32_t pack_bf2(float x, float y) {
    __nv_bfloat162 t = __floats2bfloat162_rn(x, y);
    return *(uint32_t*)&t;
}
__device__ __forceinline__ unsigned short bfu(__nv_bfloat16 h) {
    return *(unsigned short*)&h;
}

// ---------------- patchify: gather + split bf16 [hi(768)|lo(768)] ----------------
__global__ void patchify_kernel(const float* __restrict__ x, __nv_bfloat16* __restrict__ xs)
{
    int m = blockIdx.x;                 // 0..6271
    int b = m / (NP*NP);
    int p = m % (NP*NP);
    int py = p / NP, px = p % NP;
    for (int i = threadIdx.x; i < IN_DIM; i += blockDim.x) {
        int c = i >> 8;
        int r = (i >> 4) & 15;
        int s = i & 15;
        size_t src = ((size_t)(b*CC + c)*IMG + (py*PS + r))*IMG + (px*PS + s);
        float v = x[src];
        __nv_bfloat16 hi = __float2bfloat16(v);
        __nv_bfloat16 lo = __float2bfloat16(v - __bfloat162float(hi));
        xs[(size_t)m*KA1 + i]      = hi;
        xs[(size_t)m*KA1 + DD + i] = lo;
    }
}

__global__ void cls_init_kernel(const float* __restrict__ cls_emb,
                                const float* __restrict__ pos,
                                float* __restrict__ resid)
{
    int b = blockIdx.x;
    for (int d = threadIdx.x; d < DD; d += blockDim.x)
        resid[(size_t)b*SS*DD + d] = cls_emb[d] + pos[d];
}

// ---------------- weight prep: transpose + bf16 split -> [row][hi(K)|lo(K)] ----
__global__ void wprep_kernel(const float* __restrict__ W, __nv_bfloat16* __restrict__ Wp,
                             int K, int N)
{
    __shared__ float t[32][33];
    int l = blockIdx.z;
    const float* Wl = W + (size_t)l*K*N;
    __nv_bfloat16* Wpl = Wp + (size_t)l*N*2*K;
    int n0 = blockIdx.x*32, k0 = blockIdx.y*32;
    int tx = threadIdx.x, ty = threadIdx.y;

    t[ty][tx] = Wl[(size_t)(k0+ty)*N + n0+tx];
    __syncthreads();
    float v = t[tx][ty];
    int row = n0+ty, col = k0+tx;
    __nv_bfloat16 hi = __float2bfloat16(v);
    __nv_bfloat16 lo = __float2bfloat16(v - __bfloat162float(hi));
    __nv_bfloat16* dst = Wpl + (size_t)row*2*K;
    dst[col]     = hi;
    dst[K + col] = lo;
}

// ---------------- QKV weight prep (frozen: [hi|hi|lo]) ----------------
__global__ void qkv_prep_kernel(const float* __restrict__ Wq, const float* __restrict__ Wk,
                                const float* __restrict__ Wv, __nv_bfloat16* __restrict__ wout)
{
    int h = blockIdx.x, mat = blockIdx.y, l = blockIdx.z;
    const float* W = (mat == 0) ? Wq : (mat == 1) ? Wk : Wv;
    const float* Wl = W + (size_t)(l*NH + h)*64*64;
    __nv_bfloat16* dst = wout + (size_t)((l*3 + mat)*NH + h)*64*192;
    for (int idx = threadIdx.x; idx < 4096; idx += 256) {
        int e = idx >> 6, d = idx & 63;
        float v = Wl[e*64 + d];
        __nv_bfloat16 hi = __float2bfloat16(v);
        __nv_bfloat16 lo = __float2bfloat16(v - __bfloat162float(hi));
        dst[e*192 + d]       = hi;
        dst[e*192 + 64 + d]  = hi;
        dst[e*192 + 128 + d] = lo;
    }
}

// ---------------- LayerNorm (192 threads, float4) -> split bf16 [hi|lo] --------
__global__ void ln_kernel(const float* __restrict__ xin, const float* __restrict__ g,
                          const float* __restrict__ bet, __nv_bfloat16* __restrict__ xs)
{
    int row = blockIdx.x;
    int tid = threadIdx.x;                 // 0..191
    const float4* xr = (const float4*)(xin + (size_t)row*DD);
    float4 v = xr[tid];
    float s  = v.x + v.y + v.z + v.w;
    float ss = v.x*v.x + v.y*v.y + v.z*v.z + v.w*v.w;

    __shared__ float rs[6], rss[6], smv[2];
    int lane = tid & 31, w = tid >> 5;
#pragma unroll
    for (int off = 16; off; off >>= 1) {
        s  += __shfl_xor_sync(0xffffffffu, s,  off);
        ss += __shfl_xor_sync(0xffffffffu, ss, off);
    }
    if (lane == 0) { rs[w] = s; rss[w] = ss; }
    __syncthreads();
    if (tid == 0) {
        float S = 0.f, SSq = 0.f;
#pragma unroll
        for (int i = 0; i < 6; i++) { S += rs[i]; SSq += rss[i]; }
        float mean = S * (1.f/768.f);
        float var  = SSq * (1.f/768.f) - mean*mean;
        smv[0] = mean;
        smv[1] = rsqrtf(var + 1e-5f);
    }
    __syncthreads();
    float mean = smv[0], rstd = smv[1];

    float4 gg = ((const float4*)g)[tid];
    float4 bb = ((const float4*)bet)[tid];
    float y0 = (v.x - mean)*rstd*gg.x + bb.x;
    float y1 = (v.y - mean)*rstd*gg.y + bb.y;
    float y2 = (v.z - mean)*rstd*gg.z + bb.z;
    float y3 = (v.w - mean)*rstd*gg.w + bb.w;
    __nv_bfloat16 h0 = __float2bfloat16(y0);
    __nv_bfloat16 h1 = __float2bfloat16(y1);
    __nv_bfloat16 h2 = __float2bfloat16(y2);
    __nv_bfloat16 h3 = __float2bfloat16(y3);
    uint32_t hi01 = (uint32_t)bfu(h0) | ((uint32_t)bfu(h1) << 16);
    uint32_t hi23 = (uint32_t)bfu(h2) | ((uint32_t)bfu(h3) << 16);
    uint32_t lo01 = pack_bf2(y0 - __bfloat162float(h0), y1 - __bfloat162float(h1));
    uint32_t lo23 = pack_bf2(y2 - __bfloat162float(h2), y3 - __bfloat162float(h3));
    __nv_bfloat16* dst = xs + (size_t)row*KA1;
    *(uint2*)(dst + tid*4)      = make_uint2(hi01, hi23);
    *(uint2*)(dst + DD + tid*4) = make_uint2(lo01, lo23);
}

// ---------------- HMMA GEMM, 128x128 tile (GEMM1 + embed), B = [hi|lo] ---------
template<int MODE>
__global__ void __launch_bounds__(256, 2)
mma_mlp_kernel(const __nv_bfloat16* __restrict__ A, const __nv_bfloat16* __restrict__ Bw,
               const float* __restrict__ bias, __nv_bfloat16* __restrict__ hs_out,
               float* __restrict__ resid, int nk, int strideA, int strideB,
               const float* __restrict__ extra)
{
    extern __shared__ char smc[];
    const uint32_t sbase = smem_u32(smc);
    const int tid = threadIdx.x;
    const int wid = tid >> 5, lane = tid & 31;
    const int wm = wid & 1, wn = wid >> 1;
    const int bx = blockIdx.x, by = blockIdx.y;
    const int NC = 3*nk;

    const __nv_bfloat16* Abase = A + (size_t)(by*128)*strideA;
    const __nv_bfloat16* Bbase = Bw + (size_t)(bx*128)*strideB;

    float acc[4][4][4];
#pragma unroll
    for (int i = 0; i < 4; i++)
#pragma unroll
        for (int j = 0; j < 4; j++)
#pragma unroll
            for (int q = 0; q < 4; q++) acc[i][j][q] = 0.f;

    const int lq = tid & 7;
    const int lr = tid >> 3;

    auto load_chunk = [&](int c, int p) {
        int cwrap = (c < 2*nk) ? c : (c - 2*nk);          // A: [Ah|Al], 3rd pass re-reads Ah
        int bwrap = (c < nk) ? c : (c - nk);              // B: [Bh|Bl], 2nd pass re-reads Bh
        const __nv_bfloat16* Ap = Abase + (size_t)cwrap*64;
        const __nv_bfloat16* Bp = Bbase + (size_t)bwrap*64;
        uint32_t sA = sbase + p*32768;
        uint32_t sB = sA + 16384;
#pragma unroll
        for (int i = 0; i < 4; i++) {
            int r = i*32 + lr;
            uint32_t off = r*128 + lq*16;
            uint32_t sw = off ^ ((off >> 3) & 0x70);
            cp_async16(sA + sw, Ap + (size_t)r*strideA + lq*8);
            cp_async16(sB + sw, Bp + (size_t)r*strideB + lq*8);
        }
        CP_COMMIT();
    };

    const int l15 = lane & 15;
    const int lks = (lane >> 4) * 16;

    load_chunk(0, 0);

    for (int c = 0; c < NC; c++) {
        int p = c & 1;
        if (c + 1 < NC) { load_chunk(c+1, (c+1)&1); CP_WAIT1(); }
        else            { CP_WAIT0(); }
        __syncthreads();

        uint32_t sA = sbase + p*32768;
        uint32_t sB = sA + 16384;
#pragma unroll
        for (int ks = 0; ks < 4; ks++) {
            uint32_t b0[4], b1[4];
            {
                uint32_t off = (wn*32 + l15)*128 + ks*32 + lks;
                ldmx4(b0, sB + (off ^ ((off >> 3) & 0x70)));
                off = (wn*32 + 16 + l15)*128 + ks*32 + lks;
                ldmx4(b1, sB + (off ^ ((off >> 3) & 0x70)));
            }
#pragma unroll
            for (int mt = 0; mt < 4; mt++) {
                uint32_t a[4];
                uint32_t off = (wm*64 + mt*16 + l15)*128 + ks*32 + lks;
                ldmx4(a, sA + (off ^ ((off >> 3) & 0x70)));
                mma16816(acc[mt][0], a, b0[0], b0[2]);
                mma16816(acc[mt][1], a, b0[1], b0[3]);
                mma16816(acc[mt][2], a, b1[0], b1[2]);
                mma16816(acc[mt][3], a, b1[1], b1[3]);
            }
        }
        __syncthreads();
    }

    const int gm0 = by*128 + wm*64 + (lane >> 2);
    const int gn0 = bx*128 + wn*32 + (lane & 3)*2;

#pragma unroll
    for (int mt = 0; mt < 4; mt++) {
#pragma unroll
        for (int nt = 0; nt < 4; nt++) {
            int col = gn0 + nt*8;
            float bi0 = bias[col], bi1 = bias[col+1];
            int r0 = gm0 + mt*16;
            int r1 = r0 + 8;
            float v00 = acc[mt][nt][0] + bi0;
            float v01 = acc[mt][nt][1] + bi1;
            float v10 = acc[mt][nt][2] + bi0;
            float v11 = acc[mt][nt][3] + bi1;
            if (MODE == 0) {
                float g00 = 0.5f*v00*(1.f + erff(v00*0.70710678118654752f));
                float g01 = 0.5f*v01*(1.f + erff(v01*0.70710678118654752f));
                float g10 = 0.5f*v10*(1.f + erff(v10*0.70710678118654752f));
                float g11 = 0.5f*v11*(1.f + erff(v11*0.70710678118654752f));
                __nv_bfloat16 h00 = __float2bfloat16(g00);
                __nv_bfloat16 h01 = __float2bfloat16(g01);
                __nv_bfloat16 h10 = __float2bfloat16(g10);
                __nv_bfloat16 h11 = __float2bfloat16(g11);
                uint32_t hi0 = (uint32_t)bfu(h00) | ((uint32_t)bfu(h01) << 16);
                uint32_t hi1 = (uint32_t)bfu(h10) | ((uint32_t)bfu(h11) << 16);
                uint32_t lo0 = pack_bf2(g00 - __bfloat162float(h00), g01 - __bfloat162float(h01));
                uint32_t lo1 = pack_bf2(g10 - __bfloat162float(h10), g11 - __bfloat162float(h11));
                if (r0 < NTOK) {
                    *(uint32_t*)(hs_out + (size_t)r0*KA2 + col)        = hi0;
                    *(uint32_t*)(hs_out + (size_t)r0*KA2 + MLPD + col) = lo0;
                }
                if (r1 < NTOK) {
                    *(uint32_t*)(hs_out + (size_t)r1*KA2 + col)        = hi1;
                    *(uint32_t*)(hs_out + (size_t)r1*KA2 + MLPD + col) = lo1;
                }
            } else { // MODE 2: embed epilogue
                {
                    int pp = r0 % (NP*NP), bb = r0 / (NP*NP);
                    int orow = bb*SS + 1 + pp;
                    float2* p = (float2*)(resid + (size_t)orow*DD + col);
                    const float2* e = (const float2*)(extra + (size_t)(pp+1)*DD + col);
                    float2 ev = *e;
                    *p = make_float2(v00 + ev.x, v01 + ev.y);
                }
                {
                    int pp = r1 % (NP*NP), bb = r1 / (NP*NP);
                    int orow = bb*SS + 1 + pp;
                    float2* p = (float2*)(resid + (size_t)orow*DD + col);
                    const float2* e = (const float2*)(extra + (size_t)(pp+1)*DD + col);
                    float2 ev = *e;
                    *p = make_float2(v10 + ev.x, v11 + ev.y);
                }
            }
        }
    }
}

// ---------------- HMMA GEMM2: 128x64 tiles, occ 3, B = [hi|lo] ----------
__global__ void __launch_bounds__(256, 3)
mma_g2_kernel(const __nv_bfloat16* __restrict__ A, const __nv_bfloat16* __restrict__ Bw,
              const float* __restrict__ bias, float* __restrict__ resid,
              int nk, int strideA, int strideB)
{
    extern __shared__ char smc[];
    const uint32_t sbase = smem_u32(smc);
    const int tid = threadIdx.x;
    const int wid = tid >> 5, lane = tid & 31;
    const int wm = wid & 3, wn = wid >> 2;
    const int bx = blockIdx.x, by = blockIdx.y;
    const int NC = 3*nk;

    const __nv_bfloat16* Abase = A + (size_t)(by*128)*strideA;
    const __nv_bfloat16* Bbase = Bw + (size_t)(bx*64)*strideB;

    float acc[2][4][4];
#pragma unroll
    for (int i = 0; i < 2; i++)
#pragma unroll
        for (int j = 0; j < 4; j++)
#pragma unroll
            for (int q = 0; q < 4; q++) acc[i][j][q] = 0.f;

    const int lq = tid & 7;
    const int lr = tid >> 3;

    auto load_chunk = [&](int c, int p) {
        int cwrap = (c < 2*nk) ? c : (c - 2*nk);
        int bwrap = (c < nk) ? c : (c - nk);
        const __nv_bfloat16* Ap = Abase + (size_t)cwrap*64;
        const __nv_bfloat16* Bp = Bbase + (size_t)bwrap*64;
        uint32_t sA = sbase + p*24576;
        uint32_t sB = sA + 16384;
#pragma unroll
        for (int i = 0; i < 4; i++) {
            int r = i*32 + lr;
            uint32_t off = r*128 + lq*16;
            uint32_t sw = off ^ ((off >> 3) & 0x70);
            cp_async16(sA + sw, Ap + (size_t)r*strideA + lq*8);
        }
#pragma unroll
        for (int i = 0; i < 2; i++) {
            int r = i*32 + lr;
            uint32_t off = r*128 + lq*16;
            uint32_t sw = off ^ ((off >> 3) & 0x70);
            cp_async16(sB + sw, Bp + (size_t)r*strideB + lq*8);
        }
        CP_COMMIT();
    };

    const int l15 = lane & 15;
    const int lks = (lane >> 4) * 16;

    load_chunk(0, 0);

    for (int c = 0; c < NC; c++) {
        int p = c & 1;
        if (c + 1 < NC) { load_chunk(c+1, (c+1)&1); CP_WAIT1(); }
        else            { CP_WAIT0(); }
        __syncthreads();

        uint32_t sA = sbase + p*24576;
        uint32_t sB = sA + 16384;
#pragma unroll
        for (int ks = 0; ks < 4; ks++) {
            uint32_t b0[4], b1[4];
            {
                uint32_t off = (wn*32 + l15)*128 + ks*32 + lks;
                ldmx4(b0, sB + (off ^ ((off >> 3) & 0x70)));
                off = (wn*32 + 16 + l15)*128 + ks*32 + lks;
                ldmx4(b1, sB + (off ^ ((off >> 3) & 0x70)));
            }
#pragma unroll
            for (int mt = 0; mt < 2; mt++) {
                uint32_t a[4];
                uint32_t off = (wm*32 + mt*16 + l15)*128 + ks*32 + lks;
                ldmx4(a, sA + (off ^ ((off >> 3) & 0x70)));
                mma16816(acc[mt][0], a, b0[0], b0[2]);
                mma16816(acc[mt][1], a, b0[1], b0[3]);
                mma16816(acc[mt][2], a, b1[0], b1[2]);
                mma16816(acc[mt][3], a, b1[1], b1[3]);
            }
        }
        __syncthreads();
    }

    const int gm0 = by*128 + wm*32 + (lane >> 2);
    const int gn0 = bx*64 + wn*32 + (lane & 3)*2;

#pragma unroll
    for (int mt = 0; mt < 2; mt++) {
#pragma unroll
        for (int nt = 0; nt < 4; nt++) {
            int col = gn0 + nt*8;
            float bi0 = bias[col], bi1 = bias[col+1];
            int r0 = gm0 + mt*16;
            int r1 = r0 + 8;
            if (r0 < NTOK) {
                float2* p = (float2*)(resid + (size_t)r0*DD + col);
                float2 t = *p;
                t.x += acc[mt][nt][0] + bi0;
                t.y += acc[mt][nt][1] + bi1;
                *p = t;
            }
            if (r1 < NTOK) {
                float2* p = (float2*)(resid + (size_t)r1*DD + col);
                float2 t = *p;
                t.x += acc[mt][nt][2] + bi0;
                t.y += acc[mt][nt][3] + bi1;
                *p = t;
            }
        }
    }
}

// ---------------- HMMA QKV projection (FROZEN round-10/14 config) --------------
__global__ void __launch_bounds__(128, 3)
qkv_mma_kernel(const __nv_bfloat16* __restrict__ xs, const __nv_bfloat16* __restrict__ wqkv,
               const float* __restrict__ bq, const float* __restrict__ bk,
               const float* __restrict__ bv,
               __nv_bfloat16* __restrict__ qsd, __nv_bfloat16* __restrict__ ksd,
               __nv_bfloat16* __restrict__ vtd)
{
    extern __shared__ char smc[];
    const uint32_t sbase = smem_u32(smc);
    const int tid = threadIdx.x;
    const int wid = tid >> 5, lane = tid & 31;
    const int hm = blockIdx.x;
    const int mat = hm / NH, h = hm % NH;
    const int by = blockIdx.y;

    const __nv_bfloat16* Wp = wqkv + (size_t)hm*64*192;
    const float* bias = (mat == 0) ? bq : (mat == 1) ? bk : bv;

    const int lq = tid & 7, lr = tid >> 3;
#pragma unroll
    for (int c = 0; c < 2; c++) {
        const __nv_bfloat16* Ap = xs + (c ? (DD + h*64) : (h*64));
#pragma unroll
        for (int i = 0; i < 8; i++) {
            int r = i*16 + lr;
            uint32_t off = r*128 + lq*16;
            uint32_t sw = off ^ ((off >> 3) & 0x70);
            cp_async16(sbase + c*16384 + sw, Ap + (size_t)(by*128 + r)*KA1 + lq*8);
        }
    }
#pragma unroll
    for (int c = 0; c < 3; c++) {
#pragma unroll
        for (int i = 0; i < 4; i++) {
            int r = i*16 + lr;
            uint32_t off = r*128 + lq*16;
            uint32_t sw = off ^ ((off >> 3) & 0x70);
            cp_async16(sbase + 32768 + c*8192 + sw, Wp + (size_t)r*192 + c*64 + lq*8);
        }
    }
    CP_COMMIT();
    CP_WAIT0();
    __syncthreads();

    float acc[2][8][4];
#pragma unroll
    for (int i = 0; i < 2; i++)
#pragma unroll
        for (int j = 0; j < 8; j++)
#pragma unroll
            for (int t = 0; t < 4; t++) acc[i][j][t] = 0.f;

    const int l15 = lane & 15;
    const int lks = (lane >> 4) * 16;
    const int m0 = wid*32;

#pragma unroll
    for (int pass = 0; pass < 3; pass++) {
        uint32_t sA = sbase + ((pass == 1) ? 16384 : 0);
        uint32_t sB = sbase + 32768 + pass*8192;
#pragma unroll
        for (int ks = 0; ks < 4; ks++) {
            uint32_t b[4][4];
#pragma unroll
            for (int nb = 0; nb < 4; nb++) {
                uint32_t off = (nb*16 + l15)*128 + ks*32 + lks;
                ldmx4(b[nb], sB + (off ^ ((off >> 3) & 0x70)));
            }
#pragma unroll
            for (int mt = 0; mt < 2; mt++) {
                uint32_t a[4];
                uint32_t off = (m0 + mt*16 + l15)*128 + ks*32 + lks;
                ldmx4(a, sA + (off ^ ((off >> 3) & 0x70)));
#pragma unroll
                for (int nb = 0; nb < 4; nb++) {
                    mma16816(acc[mt][2*nb],   a, b[nb][0], b[nb][2]);
                    mma16816(acc[mt][2*nb+1], a, b[nb][1], b[nb][3]);
                }
            }
        }
    }

    const int c0 = (lane & 3)*2;
#pragma unroll
    for (int mt = 0; mt < 2; mt++) {
#pragma unroll
        for (int nt = 0; nt < 8; nt++) {
            int e = nt*8 + c0;
            float bi0 = bias[h*64 + e], bi1 = bias[h*64 + e + 1];
            int r0 = by*128 + m0 + mt*16 + (lane >> 2);
#pragma unroll
            for (int half = 0; half < 2; half++) {
                int r = r0 + half*8;
                if (r >= NTOK) continue;
                float v0 = acc[mt][nt][2*half]   + bi0;
                float v1 = acc[mt][nt][2*half+1] + bi1;
                __nv_bfloat16 h0 = __float2bfloat16(v0);
                __nv_bfloat16 h1 = __float2bfloat16(v1);
                float l0 = v0 - __bfloat162float(h0);
                float l1 = v1 - __bfloat162float(h1);
                int b = r / SS, s = r % SS;
                int bh = b*NH + h;
                if (mat == 2) {
                    __nv_bfloat16* vb = vtd + (size_t)bh*128*VTP;
                    vb[(size_t)e*VTP + s]          = h0;
                    vb[(size_t)(e+1)*VTP + s]      = h1;
                    vb[(size_t)(64+e)*VTP + s]     = __float2bfloat16(l0);
                    vb[(size_t)(64+e+1)*VTP + s]   = __float2bfloat16(l1);
                } else {
                    uint32_t hi = (uint32_t)bfu(h0) | ((uint32_t)bfu(h1) << 16);
                    uint32_t lo = pack_bf2(l0, l1);
                    __nv_bfloat16* base = (mat == 0 ? qsd : ksd) + ((size_t)bh*SPAD + s)*128;
                    *(uint32_t*)(base + e)      = hi;
                    *(uint32_t*)(base + 64 + e) = lo;
                }
            }
        }
    }
}

// ---------------- HMMA fused attention: dual-plane Q/K (FROZEN) ----------------
#define AK_PLANE 26624     // 208*128
__global__ void __launch_bounds__(256, 1)
attn_mma_kernel(const __nv_bfloat16* __restrict__ qsd, const __nv_bfloat16* __restrict__ ksd,
                const __nv_bfloat16* __restrict__ vtd, float* __restrict__ resid)
{
    extern __shared__ char smc[];
    const uint32_t sbase = smem_u32(smc);
    const uint32_t sQ = sbase;                         // 2 planes x 16384
    const uint32_t sK = sbase + 32768;                 // 2 planes x 26624
    const uint32_t sV = sbase + 32768 + 2*AK_PLANE;    // 128 x 464

    const int tid = threadIdx.x;
    const int wid = tid >> 5, lane = tid & 31;
    const int qt = blockIdx.x, bh = blockIdx.y;
    const int b = bh / NH, h = bh % NH;

    const __nv_bfloat16* Qg = qsd + ((size_t)bh*SPAD + (size_t)qt*128)*128;
    const __nv_bfloat16* Kg = ksd + (size_t)bh*SPAD*128;
    const __nv_bfloat16* Vg = vtd + (size_t)bh*128*VTP;

    for (int i = tid; i < 128*16; i += 256) {
        int r = i >> 4, c = i & 15;
        uint32_t pl = (c < 8) ? 0u : 16384u;
        uint32_t off = r*128 + (c & 7)*16;
        cp_async16(sQ + pl + (off ^ ((off >> 3) & 0x70)), Qg + (size_t)r*128 + c*8);
    }
    for (int i = tid; i < SPAD*16; i += 256) {
        int r = i >> 4, c = i & 15;
        uint32_t pl = (c < 8) ? 0u : (uint32_t)AK_PLANE;
        uint32_t off = r*128 + (c & 7)*16;
        cp_async16(sK + pl + (off ^ ((off >> 3) & 0x70)), Kg + (size_t)r*128 + c*8);
    }
    CP_COMMIT();
    for (int i = tid; i < 128*29; i += 256) {
        int r = i / 29, c = i % 29;
        cp_async16(sV + r*464 + c*16, Vg + (size_t)r*VTP + c*8);
    }
    CP_COMMIT();
    CP_WAIT1();
    __syncthreads();

    float s[26][4];
#pragma unroll
    for (int t = 0; t < 26; t++)
#pragma unroll
        for (int e = 0; e < 4; e++) s[t][e] = 0.f;

    const int l15 = lane & 15;
    const int lks = (lane >> 4) * 16;
    const int m0 = wid * 16;

#pragma unroll 1
    for (int kc = 0; kc < 12; kc++) {
        uint32_t qpl = (kc >= 4 && kc < 8) ? 16384u : 0u;
        uint32_t kpl = (kc >= 8) ? (uint32_t)AK_PLANE : 0u;
        int cb = (kc & 3)*32;
        uint32_t a[4];
        uint32_t off = (m0 + l15)*128 + cb + lks;
        ldmx4(a, sQ + qpl + (off ^ ((off >> 3) & 0x70)));
#pragma unroll
        for (int nb = 0; nb < 13; nb++) {
            uint32_t bb[4];
            off = (nb*16 + l15)*128 + cb + lks;
            ldmx4(bb, sK + kpl + (off ^ ((off >> 3) & 0x70)));
            mma16816(s[2*nb],   a, bb[0], bb[2]);
            mma16816(s[2*nb+1], a, bb[1], bb[3]);
        }
    }

    const int c0 = 2*(lane & 3);
    float mx0 = -1e30f, mx1 = -1e30f;
#pragma unroll
    for (int t = 0; t < 26; t++) {
        int j0 = t*8 + c0;
        float v0 = (j0   < SS) ? s[t][0]*0.125f : -1e30f;
        float v1 = (j0+1 < SS) ? s[t][1]*0.125f : -1e30f;
        float v2 = (j0   < SS) ? s[t][2]*0.125f : -1e30f;
        float v3 = (j0+1 < SS) ? s[t][3]*0.125f : -1e30f;
        s[t][0] = v0; s[t][1] = v1; s[t][2] = v2; s[t][3] = v3;
        mx0 = fmaxf(mx0, fmaxf(v0, v1));
        mx1 = fmaxf(mx1, fmaxf(v2, v3));
    }
    mx0 = fmaxf(mx0, __shfl_xor_sync(0xffffffffu, mx0, 1));
    mx0 = fmaxf(mx0, __shfl_xor_sync(0xffffffffu, mx0, 2));
    mx1 = fmaxf(mx1, __shfl_xor_sync(0xffffffffu, mx1, 1));
    mx1 = fmaxf(mx1, __shfl_xor_sync(0xffffffffu, mx1, 2));

    float sum0 = 0.f, sum1 = 0.f;
#pragma unroll
    for (int t = 0; t < 26; t++) {
        float p0 = __expf(s[t][0] - mx0);
        float p1 = __expf(s[t][1] - mx0);
        float p2 = __expf(s[t][2] - mx1);
        float p3 = __expf(s[t][3] - mx1);
        s[t][0] = p0; s[t][1] = p1; s[t][2] = p2; s[t][3] = p3;
        sum0 += p0 + p1;
        sum1 += p2 + p3;
    }
    sum0 += __shfl_xor_sync(0xffffffffu, sum0, 1);
    sum0 += __shfl_xor_sync(0xffffffffu, sum0, 2);
    sum1 += __shfl_xor_sync(0xffffffffu, sum1, 1);
    sum1 += __shfl_xor_sync(0xffffffffu, sum1, 2);
    float inv0 = 1.f / sum0, inv1 = 1.f / sum1;

    CP_WAIT0();
    __syncthreads();

    float o[8][4];
#pragma unroll
    for (int t = 0; t < 8; t++)
#pragma unroll
        for (int e = 0; e < 4; e++) o[t][e] = 0.f;

#pragma unroll 1
    for (int kt = 0; kt < 13; kt++) {
        uint32_t ah[4], al[4];
        {
            float p00 = s[2*kt][0],   p01 = s[2*kt][1],   p02 = s[2*kt][2],   p03 = s[2*kt][3];
            float p10 = s[2*kt+1][0], p11 = s[2*kt+1][1], p12 = s[2*kt+1][2], p13 = s[2*kt+1][3];
            __nv_bfloat16 h00 = __float2bfloat16(p00), h01 = __float2bfloat16(p01);
            __nv_bfloat16 h02 = __float2bfloat16(p02), h03 = __float2bfloat16(p03);
            __nv_bfloat16 h10 = __float2bfloat16(p10), h11 = __float2bfloat16(p11);
            __nv_bfloat16 h12 = __float2bfloat16(p12), h13 = __float2bfloat16(p13);
            ah[0] = (uint32_t)bfu(h00) | ((uint32_t)bfu(h01) << 16);
            ah[1] = (uint32_t)bfu(h02) | ((uint32_t)bfu(h03) << 16);
            ah[2] = (uint32_t)bfu(h10) | ((uint32_t)bfu(h11) << 16);
            ah[3] = (uint32_t)bfu(h12) | ((uint32_t)bfu(h13) << 16);
            al[0] = pack_bf2(p00 - __bfloat162float(h00), p01 - __bfloat162float(h01));
            al[1] = pack_bf2(p02 - __bfloat162float(h02), p03 - __bfloat162float(h03));
            al[2] = pack_bf2(p10 - __bfloat162float(h10), p11 - __bfloat162float(h11));
            al[3] = pack_bf2(p12 - __bfloat162float(h12), p13 - __bfloat162float(h13));
        }
#pragma unroll
        for (int nb = 0; nb < 4; nb++) {
            uint32_t bh_[4], bl_[4];
            ldmx4(bh_, sV + (nb*16 + l15)*464 + kt*32 + lks);
            ldmx4(bl_, sV + (64 + nb*16 + l15)*464 + kt*32 + lks);
            mma16816(o[2*nb],   ah, bh_[0], bh_[2]);
            mma16816(o[2*nb+1], ah, bh_[1], bh_[3]);
            mma16816(o[2*nb],   al, bh_[0], bh_[2]);
            mma16816(o[2*nb+1], al, bh_[1], bh_[3]);
            mma16816(o[2*nb],   ah, bl_[0], bl_[2]);
            mma16816(o[2*nb+1], ah, bl_[1], bl_[3]);
        }
    }

    const int r0 = qt*128 + m0 + (lane >> 2);
    const int r1 = r0 + 8;
#pragma unroll
    for (int nb = 0; nb < 8; nb++) {
        int col = h*64 + nb*8 + c0;
        if (r0 < SS) {
            float2* p = (float2*)(resid + ((size_t)(b*SS + r0))*DD + col);
            float2 t = *p;
            t.x += o[nb][0]*inv0;
            t.y += o[nb][1]*inv0;
            *p = t;
        }
        if (r1 < SS) {
            float2* p = (float2*)(resid + ((size_t)(b*SS + r1))*DD + col);
            float2 t = *p;
            t.x += o[nb][2]*inv1;
            t.y += o[nb][3]*inv1;
            *p = t;
        }
    }
}

// ---------------- classifier head: split logits GEMM + softmax ----------------
__global__ void head_gemm_kernel(const float* __restrict__ resid, const float* __restrict__ Wc,
                                 const float* __restrict__ bc, float* __restrict__ logit)
{
    __shared__ float sx[768];
    int b = blockIdx.y;
    int tid = threadIdx.x;
    for (int i = tid; i < 768; i += 128) sx[i] = resid[(size_t)b*SS*DD + i];
    __syncthreads();

    int o = blockIdx.x*128 + tid;
    if (o < OUTC) {
        float acc = bc[o];
        for (int kk = 0; kk < 768; kk++) acc += sx[kk]*Wc[(size_t)kk*OUTC + o];
        logit[(size_t)b*OUTC + o] = acc;
    }
}

__global__ void head_softmax_kernel(const float* __restrict__ logit, float* __restrict__ out)
{
    __shared__ float sl[1000];
    __shared__ float red[8];
    __shared__ float bscalar;

    int b = blockIdx.x;
    int tid = threadIdx.x;
    int lane = tid & 31, w = tid >> 5;

    for (int o = tid; o < OUTC; o += 256) sl[o] = logit[(size_t)b*OUTC + o];
    __syncthreads();

    float m = -1e30f;
    for (int o = tid; o < OUTC; o += 256) m = fmaxf(m, sl[o]);
#pragma unroll
    for (int off = 16; off; off >>= 1) m = fmaxf(m, __shfl_xor_sync(0xffffffffu, m, off));
    if (lane == 0) red[w] = m;
    __syncthreads();
    if (tid == 0) {
        float mm = red[0];
#pragma unroll
        for (int i = 1; i < 8; i++) mm = fmaxf(mm, red[i]);
        bscalar = mm;
    }
    __syncthreads();
    m = bscalar;

    float s = 0.f;
    for (int o = tid; o < OUTC; o += 256) {
        float e = __expf(sl[o] - m);
        sl[o] = e;
        s += e;
    }
#pragma unroll
    for (int off = 16; off; off >>= 1) s += __shfl_xor_sync(0xffffffffu, s, off);
    if (lane == 0) red[w] = s;
    __syncthreads();
    if (tid == 0) {
        float ssum = 0.f;
#pragma unroll
        for (int i = 0; i < 8; i++) ssum += red[i];
        bscalar = 1.f / ssum;
    }
    __syncthreads();
    float invs = bscalar;
    for (int o = tid; o < OUTC; o += 256)
        out[(size_t)b*OUTC + o] = sl[o] * invs;
}

// ---------------- launcher ----------------
extern "C" void kernel_launch(void* const* d_in, const int* in_sizes, int n_in,
                              void* d_out, int out_size)
{
    const float* x       = (const float*)d_in[0];
    const float* cls_emb = (const float*)d_in[1];
    const float* pos     = (const float*)d_in[2];
    const float* Wmap    = (const float*)d_in[3];
    const float* bmap    = (const float*)d_in[4];
    const float* ln1_g   = (const float*)d_in[5];
    const float* ln1_b   = (const float*)d_in[6];
    const float* Wq      = (const float*)d_in[7];
    const float* bq      = (const float*)d_in[8];
    const float* Wk      = (const float*)d_in[9];
    const float* bk      = (const float*)d_in[10];
    const float* Wv      = (const float*)d_in[11];
    const float* bv      = (const float*)d_in[12];
    const float* ln2_g   = (const float*)d_in[13];
    const float* ln2_b   = (const float*)d_in[14];
    const float* W1      = (const float*)d_in[15];
    const float* b1      = (const float*)d_in[16];
    const float* W2      = (const float*)d_in[17];
    const float* b2      = (const float*)d_in[18];
    const float* Wc      = (const float*)d_in[19];
    const float* bc      = (const float*)d_in[20];
    float* out = (float*)d_out;

    float *resid, *logit;
    __nv_bfloat16 *xs, *hs, *w1p, *w2p, *wmapp, *wqkv, *qsd, *ksd, *vtd;
    cudaGetSymbolAddress((void**)&resid, g_resid);
    cudaGetSymbolAddress((void**)&logit, g_logit);
    cudaGetSymbolAddress((void**)&xs,    g_xs);
    cudaGetSymbolAddress((void**)&hs,    g_hs);
    cudaGetSymbolAddress((void**)&w1p,   g_w1p);
    cudaGetSymbolAddress((void**)&w2p,   g_w2p);
    cudaGetSymbolAddress((void**)&wmapp, g_wmapp);
    cudaGetSymbolAddress((void**)&wqkv,  g_wqkv);
    cudaGetSymbolAddress((void**)&qsd,   g_qs);
    cudaGetSymbolAddress((void**)&ksd,   g_ks);
    cudaGetSymbolAddress((void**)&vtd,   g_vt);

    const int MMA_SMEM  = 65536;
    const int G2_SMEM   = 49152;
    const int QKV_SMEM  = 2*16384 + 3*8192;             // 57,344 B
    const int ATTN_SMEM = 32768 + 2*AK_PLANE + 128*464; // 145,408 B
    cudaFuncSetAttribute(mma_mlp_kernel<0>, cudaFuncAttributeMaxDynamicSharedMemorySize, MMA_SMEM);
    cudaFuncSetAttribute(mma_mlp_kernel<2>, cudaFuncAttributeMaxDynamicSharedMemorySize, MMA_SMEM);
    cudaFuncSetAttribute(mma_g2_kernel, cudaFuncAttributeMaxDynamicSharedMemorySize, G2_SMEM);
    cudaFuncSetAttribute(qkv_mma_kernel, cudaFuncAttributeMaxDynamicSharedMemorySize, QKV_SMEM);
    cudaFuncSetAttribute(attn_mma_kernel, cudaFuncAttributeMaxDynamicSharedMemorySize, ATTN_SMEM);

    // weight prep ([hi|lo] for MLP/embed; QKV frozen)
    wprep_kernel<<<dim3(MLPD/32, DD/32, LL), dim3(32,32)>>>(W1, w1p, DD, MLPD);
    wprep_kernel<<<dim3(DD/32, MLPD/32, LL), dim3(32,32)>>>(W2, w2p, MLPD, DD);
    wprep_kernel<<<dim3(DD/32, IN_DIM/32, 1), dim3(32,32)>>>(Wmap, wmapp, IN_DIM, DD);
    qkv_prep_kernel<<<dim3(NH, 3, LL), 256>>>(Wq, Wk, Wv, wqkv);

    // patch embed (split bf16 -> HMMA) + positional
    patchify_kernel<<<NPATCH, 256>>>(x, xs);
    mma_mlp_kernel<2><<<dim3(DD/128, NPATCH/128), 256, MMA_SMEM>>>(
        xs, wmapp, bmap, nullptr, resid, 12, KA1, KA1, pos);
    cls_init_kernel<<<BB, 256>>>(cls_emb, pos, resid);

    for (int l = 0; l < LL; l++) {
        ln_kernel<<<NTOK, 192>>>(resid, ln1_g + (size_t)l*DD, ln1_b + (size_t)l*DD, xs);
        qkv_mma_kernel<<<dim3(3*NH, MPAD/128), 128, QKV_SMEM>>>(
            xs, wqkv + (size_t)l*3*NH*64*192,
            bq + (size_t)l*NH*DH, bk + (size_t)l*NH*DH, bv + (size_t)l*NH*DH,
            qsd, ksd, vtd);
        attn_mma_kernel<<<dim3(2, BB*NH), 256, ATTN_SMEM>>>(qsd, ksd, vtd, resid);

        ln_kernel<<<NTOK, 192>>>(resid, ln2_g + (size_t)l*DD, ln2_b + (size_t)l*DD, xs);
        mma_mlp_kernel<0><<<dim3(MLPD/128, MPAD/128), 256, MMA_SMEM>>>(
            xs, w1p + (size_t)l*MLPD*KA1, b1 + (size_t)l*MLPD, hs, nullptr, 12, KA1, KA1, nullptr);
        mma_g2_kernel<<<dim3(DD/64, MPAD/128), 256, G2_SMEM>>>(
            hs, w2p + (size_t)l*DD*KA2, b2 + (size_t)l*DD, resid, 48, KA2, KA2);
    }

    head_gemm_kernel<<<dim3(8, BB), 128>>>(resid, Wc, bc, logit);
    head_softmax_kernel<<<BB, 256>>>(logit, out);
}